// round 1
// baseline (speedup 1.0000x reference)
#include <cuda_runtime.h>
#include <cuda_bf16.h>
#include <math.h>

// Problem constants
#define T      4096          // tokens (B*S)
#define HDIM   2048          // hidden
#define FFN    1024
#define NEXP   8
#define TOPK   2
#define SLOTS  (T * TOPK)    // 8192

// GEMM tiling
#define BM 64
#define BN 64
#define BK 16
#define NTHREADS 256

// ---------------- scratch (static device globals; no allocs allowed) ----------------
__device__ int   g_topk_idx[T * TOPK];
__device__ float g_topk_w[T * TOPK];
__device__ int   g_cnt[NEXP];
__device__ int   g_cur[NEXP];
__device__ int   g_off[NEXP + 1];
__device__ int   g_perm[SLOTS];      // slot -> token
__device__ float g_permw[SLOTS];     // slot -> routing weight
__device__ int   g_slot[T * TOPK];   // (token,k) -> slot
__device__ float g_G[(size_t)SLOTS * FFN];   // 32 MB intermediate (after SwiGLU*w)
__device__ float g_Y[(size_t)SLOTS * HDIM];  // 64 MB per-slot down-proj output

// ---------------- init ----------------
__global__ void init_kernel() {
    int i = threadIdx.x;
    if (i < NEXP) { g_cnt[i] = 0; g_cur[i] = 0; }
}

// ---------------- router: 1 warp per token, fused count ----------------
__global__ void router_kernel(const float* __restrict__ x,
                              const float* __restrict__ Wg,
                              const float* __restrict__ bias) {
    int gw   = (blockIdx.x * blockDim.x + threadIdx.x) >> 5;
    int lane = threadIdx.x & 31;
    if (gw >= T) return;
    const float* xr = x + (size_t)gw * HDIM;

    float acc[NEXP];
#pragma unroll
    for (int e = 0; e < NEXP; e++) acc[e] = 0.f;

    for (int k = lane * 4; k < HDIM; k += 32 * 4) {
        float4 xv = *(const float4*)(xr + k);
#pragma unroll
        for (int e = 0; e < NEXP; e++) {
            float4 wv = *(const float4*)(Wg + (size_t)e * HDIM + k);
            acc[e] += xv.x * wv.x + xv.y * wv.y + xv.z * wv.z + xv.w * wv.w;
        }
    }
#pragma unroll
    for (int e = 0; e < NEXP; e++) {
#pragma unroll
        for (int o = 16; o > 0; o >>= 1)
            acc[e] += __shfl_xor_sync(0xFFFFFFFFu, acc[e], o);
    }

    if (lane == 0) {
        float rw[NEXP], sc[NEXP];
#pragma unroll
        for (int e = 0; e < NEXP; e++) {
            rw[e] = 1.f / (1.f + expf(-acc[e]));
            sc[e] = rw[e] + bias[e];
        }
        // top-2, ties -> lowest index first (match jax.lax.top_k)
        int i0 = 0; float s0 = sc[0];
#pragma unroll
        for (int e = 1; e < NEXP; e++) if (sc[e] > s0) { s0 = sc[e]; i0 = e; }
        int i1 = -1; float s1 = -1e30f;
#pragma unroll
        for (int e = 0; e < NEXP; e++) {
            if (e == i0) continue;
            if (sc[e] > s1) { s1 = sc[e]; i1 = e; }
        }
        float wsum = rw[i0] + rw[i1];
        g_topk_idx[gw * 2 + 0] = i0;
        g_topk_idx[gw * 2 + 1] = i1;
        g_topk_w[gw * 2 + 0] = rw[i0] / wsum;
        g_topk_w[gw * 2 + 1] = rw[i1] / wsum;
        atomicAdd(&g_cnt[i0], 1);
        atomicAdd(&g_cnt[i1], 1);
    }
}

// ---------------- offsets (tiny prefix sum) ----------------
__global__ void offsets_kernel() {
    if (threadIdx.x == 0) {
        int acc = 0;
        g_off[0] = 0;
        for (int e = 0; e < NEXP; e++) { acc += g_cnt[e]; g_off[e + 1] = acc; }
    }
}

// ---------------- scatter tokens into per-expert contiguous slot lists ----------------
__global__ void scatter_kernel() {
    int t = blockIdx.x * blockDim.x + threadIdx.x;
    if (t >= T) return;
#pragma unroll
    for (int k = 0; k < TOPK; k++) {
        int e = g_topk_idx[t * 2 + k];
        int p = g_off[e] + atomicAdd(&g_cur[e], 1);
        g_perm[p]  = t;
        g_permw[p] = g_topk_w[t * 2 + k];
        g_slot[t * 2 + k] = p;
    }
}

// ---------------- up-projection: G = silu(X@W1^T) * (X@W3^T) * w ----------------
// grid: (FFN/BN, T/BM(worst case per expert), NEXP), block 256
__global__ __launch_bounds__(NTHREADS, 2)
void up_gemm_kernel(const float* __restrict__ x,
                    const float* __restrict__ W1,
                    const float* __restrict__ W3) {
    int e    = blockIdx.z;
    int mEnd = g_off[e + 1];
    int m0   = g_off[e] + blockIdx.y * BM;
    if (m0 >= mEnd) return;
    int n0 = blockIdx.x * BN;

    __shared__ float As [BK][BM + 4];
    __shared__ float B1s[BK][BN + 4];
    __shared__ float B3s[BK][BN + 4];

    int tid = threadIdx.x;
    int tx = tid & 15, ty = tid >> 4;
    int lr = tid >> 2;       // row (0..63) for loading
    int kq = tid & 3;        // k-quad (0..3)

    int   srow = m0 + lr;
    const float* xrow = (srow < mEnd) ? x + (size_t)g_perm[srow] * HDIM : nullptr;
    const float* b1row = W1 + ((size_t)e * FFN + (n0 + lr)) * HDIM;
    const float* b3row = W3 + ((size_t)e * FFN + (n0 + lr)) * HDIM;

    float acc1[4][4], acc3[4][4];
#pragma unroll
    for (int i = 0; i < 4; i++)
#pragma unroll
        for (int j = 0; j < 4; j++) { acc1[i][j] = 0.f; acc3[i][j] = 0.f; }

    for (int k0 = 0; k0 < HDIM; k0 += BK) {
        float4 av = make_float4(0.f, 0.f, 0.f, 0.f);
        if (xrow) av = *(const float4*)(xrow + k0 + kq * 4);
        float4 b1 = *(const float4*)(b1row + k0 + kq * 4);
        float4 b3 = *(const float4*)(b3row + k0 + kq * 4);

        As [kq * 4 + 0][lr] = av.x; As [kq * 4 + 1][lr] = av.y;
        As [kq * 4 + 2][lr] = av.z; As [kq * 4 + 3][lr] = av.w;
        B1s[kq * 4 + 0][lr] = b1.x; B1s[kq * 4 + 1][lr] = b1.y;
        B1s[kq * 4 + 2][lr] = b1.z; B1s[kq * 4 + 3][lr] = b1.w;
        B3s[kq * 4 + 0][lr] = b3.x; B3s[kq * 4 + 1][lr] = b3.y;
        B3s[kq * 4 + 2][lr] = b3.z; B3s[kq * 4 + 3][lr] = b3.w;
        __syncthreads();

#pragma unroll
        for (int kk = 0; kk < BK; kk++) {
            float a[4], p1[4], p3[4];
            *(float4*)a  = *(const float4*)&As [kk][ty * 4];
            *(float4*)p1 = *(const float4*)&B1s[kk][tx * 4];
            *(float4*)p3 = *(const float4*)&B3s[kk][tx * 4];
#pragma unroll
            for (int i = 0; i < 4; i++)
#pragma unroll
                for (int j = 0; j < 4; j++) {
                    acc1[i][j] += a[i] * p1[j];
                    acc3[i][j] += a[i] * p3[j];
                }
        }
        __syncthreads();
    }

#pragma unroll
    for (int i = 0; i < 4; i++) {
        int s = m0 + ty * 4 + i;
        if (s < mEnd) {
            float w = g_permw[s];
            float4 gv;
            float h1, h3;
            h1 = acc1[i][0]; h3 = acc3[i][0]; gv.x = (h1 / (1.f + expf(-h1))) * h3 * w;
            h1 = acc1[i][1]; h3 = acc3[i][1]; gv.y = (h1 / (1.f + expf(-h1))) * h3 * w;
            h1 = acc1[i][2]; h3 = acc3[i][2]; gv.z = (h1 / (1.f + expf(-h1))) * h3 * w;
            h1 = acc1[i][3]; h3 = acc3[i][3]; gv.w = (h1 / (1.f + expf(-h1))) * h3 * w;
            *(float4*)&g_G[(size_t)s * FFN + n0 + tx * 4] = gv;
        }
    }
}

// ---------------- down-projection: Y = G @ W2^T ----------------
// grid: (HDIM/BN, T/BM, NEXP)
__global__ __launch_bounds__(NTHREADS, 2)
void down_gemm_kernel(const float* __restrict__ W2) {
    int e    = blockIdx.z;
    int mEnd = g_off[e + 1];
    int m0   = g_off[e] + blockIdx.y * BM;
    if (m0 >= mEnd) return;
    int n0 = blockIdx.x * BN;

    __shared__ float As[BK][BM + 4];
    __shared__ float Bs[BK][BN + 4];

    int tid = threadIdx.x;
    int tx = tid & 15, ty = tid >> 4;
    int lr = tid >> 2;
    int kq = tid & 3;

    int srow = m0 + lr;
    const float* arow = (srow < mEnd) ? g_G + (size_t)srow * FFN : nullptr;
    const float* brow = W2 + ((size_t)e * HDIM + (n0 + lr)) * FFN;

    float acc[4][4];
#pragma unroll
    for (int i = 0; i < 4; i++)
#pragma unroll
        for (int j = 0; j < 4; j++) acc[i][j] = 0.f;

    for (int k0 = 0; k0 < FFN; k0 += BK) {
        float4 av = make_float4(0.f, 0.f, 0.f, 0.f);
        if (arow) av = *(const float4*)(arow + k0 + kq * 4);
        float4 bv = *(const float4*)(brow + k0 + kq * 4);

        As[kq * 4 + 0][lr] = av.x; As[kq * 4 + 1][lr] = av.y;
        As[kq * 4 + 2][lr] = av.z; As[kq * 4 + 3][lr] = av.w;
        Bs[kq * 4 + 0][lr] = bv.x; Bs[kq * 4 + 1][lr] = bv.y;
        Bs[kq * 4 + 2][lr] = bv.z; Bs[kq * 4 + 3][lr] = bv.w;
        __syncthreads();

#pragma unroll
        for (int kk = 0; kk < BK; kk++) {
            float a[4], b[4];
            *(float4*)a = *(const float4*)&As[kk][ty * 4];
            *(float4*)b = *(const float4*)&Bs[kk][tx * 4];
#pragma unroll
            for (int i = 0; i < 4; i++)
#pragma unroll
                for (int j = 0; j < 4; j++) acc[i][j] += a[i] * b[j];
        }
        __syncthreads();
    }

#pragma unroll
    for (int i = 0; i < 4; i++) {
        int s = m0 + ty * 4 + i;
        if (s < mEnd) {
            float4 yv = make_float4(acc[i][0], acc[i][1], acc[i][2], acc[i][3]);
            *(float4*)&g_Y[(size_t)s * HDIM + n0 + tx * 4] = yv;
        }
    }
}

// ---------------- deterministic pair combine: out[t] = Y[slot0] + Y[slot1] ----------------
__global__ void combine_kernel(float* __restrict__ out) {
    int idx = blockIdx.x * blockDim.x + threadIdx.x;   // over T * HDIM/4
    if (idx >= T * (HDIM / 4)) return;
    int t  = idx / (HDIM / 4);
    int hq = idx % (HDIM / 4);
    int s0 = g_slot[t * 2 + 0];
    int s1 = g_slot[t * 2 + 1];
    float4 a = *(const float4*)&g_Y[(size_t)s0 * HDIM + hq * 4];
    float4 b = *(const float4*)&g_Y[(size_t)s1 * HDIM + hq * 4];
    float4 o = make_float4(a.x + b.x, a.y + b.y, a.z + b.z, a.w + b.w);
    *(float4*)&out[(size_t)t * HDIM + hq * 4] = o;
}

// ---------------- launcher ----------------
extern "C" void kernel_launch(void* const* d_in, const int* in_sizes, int n_in,
                              void* d_out, int out_size) {
    const float* x    = (const float*)d_in[0];  // [B,S,H]
    const float* Wg   = (const float*)d_in[1];  // [E,H]
    const float* W1   = (const float*)d_in[2];  // [E,FFN,H]
    const float* W2   = (const float*)d_in[3];  // [E,H,FFN]
    const float* W3   = (const float*)d_in[4];  // [E,FFN,H]
    const float* bias = (const float*)d_in[5];  // [E]
    float* out = (float*)d_out;

    init_kernel<<<1, 32>>>();
    router_kernel<<<T / 8, 256>>>(x, Wg, bias);      // 8 warps/block
    offsets_kernel<<<1, 32>>>();
    scatter_kernel<<<(T + 255) / 256, 256>>>();

    dim3 upGrid(FFN / BN, T / BM, NEXP);             // worst-case M per expert
    up_gemm_kernel<<<upGrid, NTHREADS>>>(x, W1, W3);

    dim3 dnGrid(HDIM / BN, T / BM, NEXP);
    down_gemm_kernel<<<dnGrid, NTHREADS>>>(W2);

    combine_kernel<<<(T * (HDIM / 4) + 255) / 256, 256>>>(out);
}

// round 3
// speedup vs baseline: 2.2509x; 2.2509x over previous
#include <cuda_runtime.h>
#include <cuda_bf16.h>
#include <math.h>
#include <stdint.h>

// -------------------- problem constants --------------------
#define T      4096
#define HDIM   2048
#define FFN    1024
#define NEXP   8
#define TOPK   2
#define SLOTS  (T * TOPK)

// -------------------- scratch (device globals; no allocs) --------------------
__device__ int   g_topk_idx[T * TOPK];
__device__ float g_topk_w[T * TOPK];
__device__ int   g_cnt[NEXP];
__device__ int   g_cur[NEXP];
__device__ int   g_off[NEXP + 1];
__device__ int   g_perm[SLOTS];
__device__ float g_permw[SLOTS];
__device__ int   g_slot[T * TOPK];

__device__ __nv_bfloat16 g_x_hi [(size_t)T * HDIM];
__device__ __nv_bfloat16 g_x_lo [(size_t)T * HDIM];
__device__ __nv_bfloat16 g_w1_hi[(size_t)NEXP * FFN * HDIM];
__device__ __nv_bfloat16 g_w1_lo[(size_t)NEXP * FFN * HDIM];
__device__ __nv_bfloat16 g_w3_hi[(size_t)NEXP * FFN * HDIM];
__device__ __nv_bfloat16 g_w3_lo[(size_t)NEXP * FFN * HDIM];
__device__ __nv_bfloat16 g_w2_hi[(size_t)NEXP * HDIM * FFN];
__device__ __nv_bfloat16 g_w2_lo[(size_t)NEXP * HDIM * FFN];
__device__ __nv_bfloat16 g_G_hi [(size_t)SLOTS * FFN];
__device__ __nv_bfloat16 g_G_lo [(size_t)SLOTS * FFN];
__device__ float         g_Y    [(size_t)SLOTS * HDIM];

// -------------------- helpers --------------------
__device__ __forceinline__ uint32_t smem_u32(const void* p) {
    uint32_t a;
    asm("{ .reg .u64 t; cvta.to.shared.u64 t, %1; cvt.u32.u64 %0, t; }" : "=r"(a) : "l"(p));
    return a;
}
__device__ __forceinline__ void cpa16(uint32_t dst, const void* src, bool v) {
    uint64_t g = __cvta_generic_to_global(src);
    int sz = v ? 16 : 0;
    asm volatile("cp.async.cg.shared.global [%0], [%1], 16, %2;"
                 :: "r"(dst), "l"(g), "r"(sz) : "memory");
}
#define CP_COMMIT() asm volatile("cp.async.commit_group;" ::: "memory")
#define CP_WAIT1()  asm volatile("cp.async.wait_group 1;" ::: "memory")
#define CP_WAIT0()  asm volatile("cp.async.wait_group 0;" ::: "memory")

#define LDM4(r, a) \
    asm volatile("ldmatrix.sync.aligned.m8n8.x4.shared.b16 {%0,%1,%2,%3}, [%4];" \
        : "=r"((r)[0]), "=r"((r)[1]), "=r"((r)[2]), "=r"((r)[3]) : "r"(a))

#define MMA(d, a, b0, b1) \
    asm volatile("mma.sync.aligned.m16n8k16.row.col.f32.bf16.bf16.f32 " \
        "{%0,%1,%2,%3},{%4,%5,%6,%7},{%8,%9},{%0,%1,%2,%3};" \
        : "+f"((d)[0]), "+f"((d)[1]), "+f"((d)[2]), "+f"((d)[3]) \
        : "r"((a)[0]), "r"((a)[1]), "r"((a)[2]), "r"((a)[3]), "r"(b0), "r"(b1))

// smem row stride: 32 bf16 data + 8 pad = 40 elems = 80 bytes (conflict-free ldmatrix)
#define SROW 80

// -------------------- small kernels --------------------
__global__ void init_kernel() {
    int i = threadIdx.x;
    if (i < NEXP) { g_cnt[i] = 0; g_cur[i] = 0; }
}

__global__ void convert_kernel(const float* __restrict__ s,
                               __nv_bfloat16* __restrict__ hi,
                               __nv_bfloat16* __restrict__ lo, int n4) {
    int i = blockIdx.x * blockDim.x + threadIdx.x;
    if (i >= n4) return;
    float4 v = ((const float4*)s)[i];
    __nv_bfloat16 h0 = __float2bfloat16(v.x), h1 = __float2bfloat16(v.y);
    __nv_bfloat16 h2 = __float2bfloat16(v.z), h3 = __float2bfloat16(v.w);
    __nv_bfloat16 l0 = __float2bfloat16(v.x - __bfloat162float(h0));
    __nv_bfloat16 l1 = __float2bfloat16(v.y - __bfloat162float(h1));
    __nv_bfloat16 l2 = __float2bfloat16(v.z - __bfloat162float(h2));
    __nv_bfloat16 l3 = __float2bfloat16(v.w - __bfloat162float(h3));
    ((__nv_bfloat162*)hi)[i * 2 + 0] = __halves2bfloat162(h0, h1);
    ((__nv_bfloat162*)hi)[i * 2 + 1] = __halves2bfloat162(h2, h3);
    ((__nv_bfloat162*)lo)[i * 2 + 0] = __halves2bfloat162(l0, l1);
    ((__nv_bfloat162*)lo)[i * 2 + 1] = __halves2bfloat162(l2, l3);
}

__global__ void router_kernel(const float* __restrict__ x,
                              const float* __restrict__ Wg,
                              const float* __restrict__ bias) {
    int gw   = (blockIdx.x * blockDim.x + threadIdx.x) >> 5;
    int lane = threadIdx.x & 31;
    if (gw >= T) return;
    const float* xr = x + (size_t)gw * HDIM;
    float acc[NEXP];
#pragma unroll
    for (int e = 0; e < NEXP; e++) acc[e] = 0.f;
    for (int k = lane * 4; k < HDIM; k += 32 * 4) {
        float4 xv = *(const float4*)(xr + k);
#pragma unroll
        for (int e = 0; e < NEXP; e++) {
            float4 wv = *(const float4*)(Wg + (size_t)e * HDIM + k);
            acc[e] += xv.x * wv.x + xv.y * wv.y + xv.z * wv.z + xv.w * wv.w;
        }
    }
#pragma unroll
    for (int e = 0; e < NEXP; e++) {
#pragma unroll
        for (int o = 16; o > 0; o >>= 1)
            acc[e] += __shfl_xor_sync(0xFFFFFFFFu, acc[e], o);
    }
    if (lane == 0) {
        float rw[NEXP], sc[NEXP];
#pragma unroll
        for (int e = 0; e < NEXP; e++) {
            rw[e] = 1.f / (1.f + expf(-acc[e]));
            sc[e] = rw[e] + bias[e];
        }
        int i0 = 0; float s0 = sc[0];
#pragma unroll
        for (int e = 1; e < NEXP; e++) if (sc[e] > s0) { s0 = sc[e]; i0 = e; }
        int i1 = -1; float s1 = -1e30f;
#pragma unroll
        for (int e = 0; e < NEXP; e++) {
            if (e == i0) continue;
            if (sc[e] > s1) { s1 = sc[e]; i1 = e; }
        }
        float wsum = rw[i0] + rw[i1];
        g_topk_idx[gw * 2 + 0] = i0;
        g_topk_idx[gw * 2 + 1] = i1;
        g_topk_w[gw * 2 + 0] = rw[i0] / wsum;
        g_topk_w[gw * 2 + 1] = rw[i1] / wsum;
        atomicAdd(&g_cnt[i0], 1);
        atomicAdd(&g_cnt[i1], 1);
    }
}

__global__ void offsets_kernel() {
    if (threadIdx.x == 0) {
        int acc = 0;
        g_off[0] = 0;
        for (int e = 0; e < NEXP; e++) { acc += g_cnt[e]; g_off[e + 1] = acc; }
    }
}

__global__ void scatter_kernel() {
    int t = blockIdx.x * blockDim.x + threadIdx.x;
    if (t >= T) return;
#pragma unroll
    for (int k = 0; k < TOPK; k++) {
        int e = g_topk_idx[t * 2 + k];
        int p = g_off[e] + atomicAdd(&g_cur[e], 1);
        g_perm[p]  = t;
        g_permw[p] = g_topk_w[t * 2 + k];
        g_slot[t * 2 + k] = p;
    }
}

// -------------------- up GEMM: 128M x 64N, W1+W3, K=HDIM --------------------
#define UP_AH  0
#define UP_AL  (128 * SROW)
#define UP_B1H (2 * 128 * SROW)
#define UP_B1L (UP_B1H + 64 * SROW)
#define UP_B3H (UP_B1L + 64 * SROW)
#define UP_B3L (UP_B3H + 64 * SROW)
#define UP_STAGE (UP_B3L + 64 * SROW)        // 40960 B
#define UP_SMEM  (2 * UP_STAGE)

__global__ __launch_bounds__(256) void up_mm() {
    int e    = blockIdx.z;
    int mEnd = g_off[e + 1];
    int m0   = g_off[e] + blockIdx.y * 128;
    if (m0 >= mEnd) return;
    int n0 = blockIdx.x * 64;

    extern __shared__ char smem[];
    uint32_t sb = smem_u32(smem);
    int tid = threadIdx.x, lane = tid & 31, wid = tid >> 5;

    // ---- loader setup: thread owns rows r0, r0+64; 16B seg ----
    int r0 = tid >> 2, seg = tid & 3;
    int slot0 = m0 + r0, slot1 = m0 + r0 + 64;
    bool v0 = slot0 < mEnd, v1 = slot1 < mEnd;
    int tok0 = v0 ? g_perm[slot0] : 0;
    int tok1 = v1 ? g_perm[slot1] : 0;
    const __nv_bfloat16* xh0 = g_x_hi + (size_t)tok0 * HDIM + seg * 8;
    const __nv_bfloat16* xh1 = g_x_hi + (size_t)tok1 * HDIM + seg * 8;
    const __nv_bfloat16* xl0 = g_x_lo + (size_t)tok0 * HDIM + seg * 8;
    const __nv_bfloat16* xl1 = g_x_lo + (size_t)tok1 * HDIM + seg * 8;
    size_t browo = ((size_t)e * FFN + n0 + r0) * HDIM + seg * 8;
    const __nv_bfloat16* b1h = g_w1_hi + browo;
    const __nv_bfloat16* b1l = g_w1_lo + browo;
    const __nv_bfloat16* b3h = g_w3_hi + browo;
    const __nv_bfloat16* b3l = g_w3_lo + browo;

    uint32_t dA0 = sb + r0 * SROW + seg * 16;
    uint32_t dA1 = dA0 + 64 * SROW;

#define UP_LOAD(buf, kb) do {                                   \
        uint32_t o_ = (buf) * UP_STAGE;                         \
        cpa16(dA0 + o_ + UP_AH,  xh0 + (kb), v0);               \
        cpa16(dA1 + o_ + UP_AH,  xh1 + (kb), v1);               \
        cpa16(dA0 + o_ + UP_AL,  xl0 + (kb), v0);               \
        cpa16(dA1 + o_ + UP_AL,  xl1 + (kb), v1);               \
        cpa16(dA0 + o_ + UP_B1H, b1h + (kb), true);             \
        cpa16(dA0 + o_ + UP_B1L, b1l + (kb), true);             \
        cpa16(dA0 + o_ + UP_B3H, b3h + (kb), true);             \
        cpa16(dA0 + o_ + UP_B3L, b3l + (kb), true);             \
        CP_COMMIT();                                            \
    } while (0)

    // ---- compute setup ----
    int warpM = wid & 3, warpN = wid >> 2;
    uint32_t aOff = (uint32_t)((lane & 15) * SROW + (lane >> 4) * 16);
    uint32_t bOff = (uint32_t)(((lane & 7) + ((lane >> 4) << 3)) * SROW + ((lane >> 3) & 1) * 16);

    float acc1[2][4][4], acc3[2][4][4];
#pragma unroll
    for (int i = 0; i < 2; i++)
#pragma unroll
        for (int j = 0; j < 4; j++)
#pragma unroll
            for (int q = 0; q < 4; q++) { acc1[i][j][q] = 0.f; acc3[i][j][q] = 0.f; }

    UP_LOAD(0, 0);
    const int NCH = HDIM / 32;
#pragma unroll 1
    for (int c = 0; c < NCH; c++) {
        int buf = c & 1;
        if (c + 1 < NCH) { UP_LOAD(buf ^ 1, (c + 1) * 32); CP_WAIT1(); }
        else             { CP_WAIT0(); }
        __syncthreads();

        uint32_t s0  = sb + buf * UP_STAGE;
        uint32_t aH  = s0 + UP_AH  + (warpM * 32) * SROW + aOff;
        uint32_t aL  = s0 + UP_AL  + (warpM * 32) * SROW + aOff;
        uint32_t b1H = s0 + UP_B1H + (warpN * 32) * SROW + bOff;
        uint32_t b1L = s0 + UP_B1L + (warpN * 32) * SROW + bOff;
        uint32_t b3H = s0 + UP_B3H + (warpN * 32) * SROW + bOff;
        uint32_t b3L = s0 + UP_B3L + (warpN * 32) * SROW + bOff;

#pragma unroll
        for (int ks = 0; ks < 2; ks++) {
            uint32_t ah[2][4], al[2][4];
            LDM4(ah[0], aH + ks * 32);
            LDM4(ah[1], aH + 16 * SROW + ks * 32);
            LDM4(al[0], aL + ks * 32);
            LDM4(al[1], aL + 16 * SROW + ks * 32);
#pragma unroll
            for (int jp = 0; jp < 2; jp++) {
                uint32_t bh[4], bl[4];
                LDM4(bh, b1H + jp * 16 * SROW + ks * 32);
                LDM4(bl, b1L + jp * 16 * SROW + ks * 32);
#pragma unroll
                for (int i = 0; i < 2; i++) {
                    MMA(acc1[i][2 * jp],     ah[i], bh[0], bh[1]);
                    MMA(acc1[i][2 * jp],     ah[i], bl[0], bl[1]);
                    MMA(acc1[i][2 * jp],     al[i], bh[0], bh[1]);
                    MMA(acc1[i][2 * jp + 1], ah[i], bh[2], bh[3]);
                    MMA(acc1[i][2 * jp + 1], ah[i], bl[2], bl[3]);
                    MMA(acc1[i][2 * jp + 1], al[i], bh[2], bh[3]);
                }
            }
#pragma unroll
            for (int jp = 0; jp < 2; jp++) {
                uint32_t bh[4], bl[4];
                LDM4(bh, b3H + jp * 16 * SROW + ks * 32);
                LDM4(bl, b3L + jp * 16 * SROW + ks * 32);
#pragma unroll
                for (int i = 0; i < 2; i++) {
                    MMA(acc3[i][2 * jp],     ah[i], bh[0], bh[1]);
                    MMA(acc3[i][2 * jp],     ah[i], bl[0], bl[1]);
                    MMA(acc3[i][2 * jp],     al[i], bh[0], bh[1]);
                    MMA(acc3[i][2 * jp + 1], ah[i], bh[2], bh[3]);
                    MMA(acc3[i][2 * jp + 1], ah[i], bl[2], bl[3]);
                    MMA(acc3[i][2 * jp + 1], al[i], bh[2], bh[3]);
                }
            }
        }
        __syncthreads();
    }

    // ---- epilogue: SwiGLU * weight -> G hi/lo ----
    int rb = warpM * 32 + (lane >> 2);
#pragma unroll
    for (int i = 0; i < 2; i++) {
#pragma unroll
        for (int h = 0; h < 2; h++) {
            int r = rb + i * 16 + h * 8;
            int slot = m0 + r;
            if (slot < mEnd) {
                float w = g_permw[slot];
                size_t rowoff = (size_t)slot * FFN;
#pragma unroll
                for (int j = 0; j < 4; j++) {
                    float d1a = acc1[i][j][2 * h], d1b = acc1[i][j][2 * h + 1];
                    float d3a = acc3[i][j][2 * h], d3b = acc3[i][j][2 * h + 1];
                    float ga = d1a / (1.f + expf(-d1a)) * d3a * w;
                    float gb = d1b / (1.f + expf(-d1b)) * d3b * w;
                    __nv_bfloat16 ha = __float2bfloat16(ga), hb = __float2bfloat16(gb);
                    __nv_bfloat16 la = __float2bfloat16(ga - __bfloat162float(ha));
                    __nv_bfloat16 lb = __float2bfloat16(gb - __bfloat162float(hb));
                    int cc = n0 + warpN * 32 + j * 8 + (lane & 3) * 2;
                    *(__nv_bfloat162*)(g_G_hi + rowoff + cc) = __halves2bfloat162(ha, hb);
                    *(__nv_bfloat162*)(g_G_lo + rowoff + cc) = __halves2bfloat162(la, lb);
                }
            }
        }
    }
#undef UP_LOAD
}

// -------------------- down GEMM: 128M x 128N, K=FFN --------------------
#define DN_AH  0
#define DN_AL  (128 * SROW)
#define DN_BH  (2 * 128 * SROW)
#define DN_BL  (3 * 128 * SROW)
#define DN_STAGE (4 * 128 * SROW)            // 40960 B
#define DN_SMEM  (2 * DN_STAGE)

__global__ __launch_bounds__(256) void down_mm() {
    int e    = blockIdx.z;
    int mEnd = g_off[e + 1];
    int m0   = g_off[e] + blockIdx.y * 128;
    if (m0 >= mEnd) return;
    int n0 = blockIdx.x * 128;

    extern __shared__ char smem[];
    uint32_t sb = smem_u32(smem);
    int tid = threadIdx.x, lane = tid & 31, wid = tid >> 5;

    int r0 = tid >> 2, seg = tid & 3;
    int slot0 = m0 + r0, slot1 = m0 + r0 + 64;
    bool v0 = slot0 < mEnd, v1 = slot1 < mEnd;
    const __nv_bfloat16* ah0 = g_G_hi + (size_t)(v0 ? slot0 : 0) * FFN + seg * 8;
    const __nv_bfloat16* ah1 = g_G_hi + (size_t)(v1 ? slot1 : 0) * FFN + seg * 8;
    const __nv_bfloat16* al0 = g_G_lo + (size_t)(v0 ? slot0 : 0) * FFN + seg * 8;
    const __nv_bfloat16* al1 = g_G_lo + (size_t)(v1 ? slot1 : 0) * FFN + seg * 8;
    size_t brow0 = ((size_t)e * HDIM + n0 + r0) * FFN + seg * 8;
    size_t brow1 = ((size_t)e * HDIM + n0 + r0 + 64) * FFN + seg * 8;
    const __nv_bfloat16* bh0 = g_w2_hi + brow0;
    const __nv_bfloat16* bh1 = g_w2_hi + brow1;
    const __nv_bfloat16* bl0 = g_w2_lo + brow0;
    const __nv_bfloat16* bl1 = g_w2_lo + brow1;

    uint32_t d0 = sb + r0 * SROW + seg * 16;
    uint32_t d1 = d0 + 64 * SROW;

#define DN_LOAD(buf, kb) do {                                   \
        uint32_t o_ = (buf) * DN_STAGE;                         \
        cpa16(d0 + o_ + DN_AH, ah0 + (kb), v0);                 \
        cpa16(d1 + o_ + DN_AH, ah1 + (kb), v1);                 \
        cpa16(d0 + o_ + DN_AL, al0 + (kb), v0);                 \
        cpa16(d1 + o_ + DN_AL, al1 + (kb), v1);                 \
        cpa16(d0 + o_ + DN_BH, bh0 + (kb), true);               \
        cpa16(d1 + o_ + DN_BH, bh1 + (kb), true);               \
        cpa16(d0 + o_ + DN_BL, bl0 + (kb), true);               \
        cpa16(d1 + o_ + DN_BL, bl1 + (kb), true);               \
        CP_COMMIT();                                            \
    } while (0)

    int warpM = wid & 3, warpN = wid >> 2;
    uint32_t aOff = (uint32_t)((lane & 15) * SROW + (lane >> 4) * 16);
    uint32_t bOff = (uint32_t)(((lane & 7) + ((lane >> 4) << 3)) * SROW + ((lane >> 3) & 1) * 16);

    float acc[2][8][4];
#pragma unroll
    for (int i = 0; i < 2; i++)
#pragma unroll
        for (int j = 0; j < 8; j++)
#pragma unroll
            for (int q = 0; q < 4; q++) acc[i][j][q] = 0.f;

    DN_LOAD(0, 0);
    const int NCH = FFN / 32;
#pragma unroll 1
    for (int c = 0; c < NCH; c++) {
        int buf = c & 1;
        if (c + 1 < NCH) { DN_LOAD(buf ^ 1, (c + 1) * 32); CP_WAIT1(); }
        else             { CP_WAIT0(); }
        __syncthreads();

        uint32_t s0 = sb + buf * DN_STAGE;
        uint32_t aH = s0 + DN_AH + (warpM * 32) * SROW + aOff;
        uint32_t aL = s0 + DN_AL + (warpM * 32) * SROW + aOff;
        uint32_t bH = s0 + DN_BH + (warpN * 64) * SROW + bOff;
        uint32_t bL = s0 + DN_BL + (warpN * 64) * SROW + bOff;

#pragma unroll
        for (int ks = 0; ks < 2; ks++) {
            uint32_t ah[2][4], al[2][4];
            LDM4(ah[0], aH + ks * 32);
            LDM4(ah[1], aH + 16 * SROW + ks * 32);
            LDM4(al[0], aL + ks * 32);
            LDM4(al[1], aL + 16 * SROW + ks * 32);
#pragma unroll
            for (int jp = 0; jp < 4; jp++) {
                uint32_t bh[4], bl[4];
                LDM4(bh, bH + jp * 16 * SROW + ks * 32);
                LDM4(bl, bL + jp * 16 * SROW + ks * 32);
#pragma unroll
                for (int i = 0; i < 2; i++) {
                    MMA(acc[i][2 * jp],     ah[i], bh[0], bh[1]);
                    MMA(acc[i][2 * jp],     ah[i], bl[0], bl[1]);
                    MMA(acc[i][2 * jp],     al[i], bh[0], bh[1]);
                    MMA(acc[i][2 * jp + 1], ah[i], bh[2], bh[3]);
                    MMA(acc[i][2 * jp + 1], ah[i], bl[2], bl[3]);
                    MMA(acc[i][2 * jp + 1], al[i], bh[2], bh[3]);
                }
            }
        }
        __syncthreads();
    }

    int rb = warpM * 32 + (lane >> 2);
#pragma unroll
    for (int i = 0; i < 2; i++) {
#pragma unroll
        for (int h = 0; h < 2; h++) {
            int r = rb + i * 16 + h * 8;
            int slot = m0 + r;
            if (slot < mEnd) {
                float* yrow = g_Y + (size_t)slot * HDIM;
#pragma unroll
                for (int j = 0; j < 8; j++) {
                    int cc = n0 + warpN * 64 + j * 8 + (lane & 3) * 2;
                    *(float2*)(yrow + cc) =
                        make_float2(acc[i][j][2 * h], acc[i][j][2 * h + 1]);
                }
            }
        }
    }
#undef DN_LOAD
}

// -------------------- combine --------------------
__global__ void combine_kernel(float* __restrict__ out) {
    int idx = blockIdx.x * blockDim.x + threadIdx.x;
    if (idx >= T * (HDIM / 4)) return;
    int t  = idx / (HDIM / 4);
    int hq = idx % (HDIM / 4);
    int s0 = g_slot[t * 2 + 0];
    int s1 = g_slot[t * 2 + 1];
    float4 a = *(const float4*)&g_Y[(size_t)s0 * HDIM + hq * 4];
    float4 b = *(const float4*)&g_Y[(size_t)s1 * HDIM + hq * 4];
    *(float4*)&out[(size_t)t * HDIM + hq * 4] =
        make_float4(a.x + b.x, a.y + b.y, a.z + b.z, a.w + b.w);
}

// -------------------- launcher --------------------
extern "C" void kernel_launch(void* const* d_in, const int* in_sizes, int n_in,
                              void* d_out, int out_size) {
    const float* x    = (const float*)d_in[0];
    const float* Wg   = (const float*)d_in[1];
    const float* W1   = (const float*)d_in[2];
    const float* W2   = (const float*)d_in[3];
    const float* W3   = (const float*)d_in[4];
    const float* bias = (const float*)d_in[5];
    float* out = (float*)d_out;

    cudaFuncSetAttribute(up_mm,   cudaFuncAttributeMaxDynamicSharedMemorySize, UP_SMEM);
    cudaFuncSetAttribute(down_mm, cudaFuncAttributeMaxDynamicSharedMemorySize, DN_SMEM);

    {
        __nv_bfloat16 *xh, *xl, *w1h, *w1l, *w3h, *w3l, *w2h, *w2l;
        cudaGetSymbolAddress((void**)&xh,  g_x_hi);  cudaGetSymbolAddress((void**)&xl,  g_x_lo);
        cudaGetSymbolAddress((void**)&w1h, g_w1_hi); cudaGetSymbolAddress((void**)&w1l, g_w1_lo);
        cudaGetSymbolAddress((void**)&w3h, g_w3_hi); cudaGetSymbolAddress((void**)&w3l, g_w3_lo);
        cudaGetSymbolAddress((void**)&w2h, g_w2_hi); cudaGetSymbolAddress((void**)&w2l, g_w2_lo);
        int nx = T * HDIM / 4, nw = NEXP * FFN * HDIM / 4;
        convert_kernel<<<(nx + 255) / 256, 256>>>(x,  xh,  xl,  nx);
        convert_kernel<<<(nw + 255) / 256, 256>>>(W1, w1h, w1l, nw);
        convert_kernel<<<(nw + 255) / 256, 256>>>(W3, w3h, w3l, nw);
        convert_kernel<<<(nw + 255) / 256, 256>>>(W2, w2h, w2l, nw);
    }

    init_kernel<<<1, 32>>>();
    router_kernel<<<T / 8, 256>>>(x, Wg, bias);
    offsets_kernel<<<1, 32>>>();
    scatter_kernel<<<(T + 255) / 256, 256>>>();

    dim3 upGrid(FFN / 64, T / 128, NEXP);
    up_mm<<<upGrid, 256, UP_SMEM>>>();

    dim3 dnGrid(HDIM / 128, T / 128, NEXP);
    down_mm<<<dnGrid, 256, DN_SMEM>>>();

    combine_kernel<<<(T * (HDIM / 4) + 255) / 256, 256>>>(out);
}

// round 4
// speedup vs baseline: 2.3560x; 1.0467x over previous
#include <cuda_runtime.h>
#include <cuda_bf16.h>
#include <math.h>
#include <stdint.h>

// -------------------- problem constants --------------------
#define T      4096
#define HDIM   2048
#define FFN    1024
#define NEXP   8
#define TOPK   2
#define SLOTS  (T * TOPK)

// -------------------- scratch (device globals; no allocs) --------------------
__device__ int   g_topk_idx[T * TOPK];
__device__ float g_topk_w[T * TOPK];
__device__ int   g_cnt[NEXP];
__device__ int   g_cur[NEXP];
__device__ int   g_off[NEXP + 1];
__device__ int   g_perm[SLOTS];
__device__ float g_permw[SLOTS];
__device__ int   g_slot[T * TOPK];

__device__ __nv_bfloat16 g_x_hi [(size_t)T * HDIM];
__device__ __nv_bfloat16 g_x_lo [(size_t)T * HDIM];
__device__ __nv_bfloat16 g_w1_hi[(size_t)NEXP * FFN * HDIM];
__device__ __nv_bfloat16 g_w1_lo[(size_t)NEXP * FFN * HDIM];
__device__ __nv_bfloat16 g_w3_hi[(size_t)NEXP * FFN * HDIM];
__device__ __nv_bfloat16 g_w3_lo[(size_t)NEXP * FFN * HDIM];
__device__ __nv_bfloat16 g_w2_hi[(size_t)NEXP * HDIM * FFN];
__device__ __nv_bfloat16 g_w2_lo[(size_t)NEXP * HDIM * FFN];
__device__ __nv_bfloat16 g_G_hi [(size_t)SLOTS * FFN];
__device__ __nv_bfloat16 g_G_lo [(size_t)SLOTS * FFN];
__device__ float         g_Y    [(size_t)SLOTS * HDIM];

// -------------------- helpers --------------------
__device__ __forceinline__ uint32_t smem_u32(const void* p) {
    uint32_t a;
    asm("{ .reg .u64 t; cvta.to.shared.u64 t, %1; cvt.u32.u64 %0, t; }" : "=r"(a) : "l"(p));
    return a;
}
__device__ __forceinline__ void cpa16(uint32_t dst, const void* src, bool v) {
    uint64_t g = __cvta_generic_to_global(src);
    int sz = v ? 16 : 0;
    asm volatile("cp.async.cg.shared.global [%0], [%1], 16, %2;"
                 :: "r"(dst), "l"(g), "r"(sz) : "memory");
}
#define CP_COMMIT() asm volatile("cp.async.commit_group;" ::: "memory")
#define CP_WAIT2()  asm volatile("cp.async.wait_group 2;" ::: "memory")

#define LDM4(r, a) \
    asm volatile("ldmatrix.sync.aligned.m8n8.x4.shared.b16 {%0,%1,%2,%3}, [%4];" \
        : "=r"((r)[0]), "=r"((r)[1]), "=r"((r)[2]), "=r"((r)[3]) : "r"(a))

#define MMA(d, a, b0, b1) \
    asm volatile("mma.sync.aligned.m16n8k16.row.col.f32.bf16.bf16.f32 " \
        "{%0,%1,%2,%3},{%4,%5,%6,%7},{%8,%9},{%0,%1,%2,%3};" \
        : "+f"((d)[0]), "+f"((d)[1]), "+f"((d)[2]), "+f"((d)[3]) \
        : "r"((a)[0]), "r"((a)[1]), "r"((a)[2]), "r"((a)[3]), "r"(b0), "r"(b1))

// smem row stride: 32 bf16 data + 8 pad = 80 bytes (conflict-free ldmatrix)
#define SROW 80

// -------------------- init --------------------
__global__ void init_kernel() {
    int i = threadIdx.x;
    if (i < NEXP) { g_cnt[i] = 0; g_cur[i] = 0; }
}

// -------------------- fused hi/lo conversion for x, W1, W3, W2 --------------------
__global__ void convert_all(const float* __restrict__ x, const float* __restrict__ W1,
                            const float* __restrict__ W3, const float* __restrict__ W2) {
    const size_t nx = (size_t)T * HDIM / 4;
    const size_t nw = (size_t)NEXP * FFN * HDIM / 4;
    size_t i = (size_t)blockIdx.x * blockDim.x + threadIdx.x;
    const float* s; __nv_bfloat16 *hi, *lo; size_t j;
    if (i < nx)               { s = x;  hi = g_x_hi;  lo = g_x_lo;  j = i; }
    else if (i < nx + nw)     { s = W1; hi = g_w1_hi; lo = g_w1_lo; j = i - nx; }
    else if (i < nx + 2 * nw) { s = W3; hi = g_w3_hi; lo = g_w3_lo; j = i - nx - nw; }
    else if (i < nx + 3 * nw) { s = W2; hi = g_w2_hi; lo = g_w2_lo; j = i - nx - 2 * nw; }
    else return;
    float4 v = ((const float4*)s)[j];
    __nv_bfloat16 h0 = __float2bfloat16(v.x), h1 = __float2bfloat16(v.y);
    __nv_bfloat16 h2 = __float2bfloat16(v.z), h3 = __float2bfloat16(v.w);
    __nv_bfloat16 l0 = __float2bfloat16(v.x - __bfloat162float(h0));
    __nv_bfloat16 l1 = __float2bfloat16(v.y - __bfloat162float(h1));
    __nv_bfloat16 l2 = __float2bfloat16(v.z - __bfloat162float(h2));
    __nv_bfloat16 l3 = __float2bfloat16(v.w - __bfloat162float(h3));
    ((__nv_bfloat162*)hi)[j * 2 + 0] = __halves2bfloat162(h0, h1);
    ((__nv_bfloat162*)hi)[j * 2 + 1] = __halves2bfloat162(h2, h3);
    ((__nv_bfloat162*)lo)[j * 2 + 0] = __halves2bfloat162(l0, l1);
    ((__nv_bfloat162*)lo)[j * 2 + 1] = __halves2bfloat162(l2, l3);
}

// -------------------- router --------------------
__global__ void router_kernel(const float* __restrict__ x,
                              const float* __restrict__ Wg,
                              const float* __restrict__ bias) {
    int gw   = (blockIdx.x * blockDim.x + threadIdx.x) >> 5;
    int lane = threadIdx.x & 31;
    if (gw >= T) return;
    const float* xr = x + (size_t)gw * HDIM;
    float acc[NEXP];
#pragma unroll
    for (int e = 0; e < NEXP; e++) acc[e] = 0.f;
    for (int k = lane * 4; k < HDIM; k += 32 * 4) {
        float4 xv = *(const float4*)(xr + k);
#pragma unroll
        for (int e = 0; e < NEXP; e++) {
            float4 wv = *(const float4*)(Wg + (size_t)e * HDIM + k);
            acc[e] += xv.x * wv.x + xv.y * wv.y + xv.z * wv.z + xv.w * wv.w;
        }
    }
#pragma unroll
    for (int e = 0; e < NEXP; e++) {
#pragma unroll
        for (int o = 16; o > 0; o >>= 1)
            acc[e] += __shfl_xor_sync(0xFFFFFFFFu, acc[e], o);
    }
    if (lane == 0) {
        float rw[NEXP], sc[NEXP];
#pragma unroll
        for (int e = 0; e < NEXP; e++) {
            rw[e] = 1.f / (1.f + expf(-acc[e]));
            sc[e] = rw[e] + bias[e];
        }
        int i0 = 0; float s0 = sc[0];
#pragma unroll
        for (int e = 1; e < NEXP; e++) if (sc[e] > s0) { s0 = sc[e]; i0 = e; }
        int i1 = -1; float s1 = -1e30f;
#pragma unroll
        for (int e = 0; e < NEXP; e++) {
            if (e == i0) continue;
            if (sc[e] > s1) { s1 = sc[e]; i1 = e; }
        }
        float wsum = rw[i0] + rw[i1];
        g_topk_idx[gw * 2 + 0] = i0;
        g_topk_idx[gw * 2 + 1] = i1;
        g_topk_w[gw * 2 + 0] = rw[i0] / wsum;
        g_topk_w[gw * 2 + 1] = rw[i1] / wsum;
        atomicAdd(&g_cnt[i0], 1);
        atomicAdd(&g_cnt[i1], 1);
    }
}

__global__ void offsets_kernel() {
    if (threadIdx.x == 0) {
        int acc = 0;
        g_off[0] = 0;
        for (int e = 0; e < NEXP; e++) { acc += g_cnt[e]; g_off[e + 1] = acc; }
    }
}

__global__ void scatter_kernel() {
    int t = blockIdx.x * blockDim.x + threadIdx.x;
    if (t >= T) return;
#pragma unroll
    for (int k = 0; k < TOPK; k++) {
        int e = g_topk_idx[t * 2 + k];
        int p = g_off[e] + atomicAdd(&g_cur[e], 1);
        g_perm[p]  = t;
        g_permw[p] = g_topk_w[t * 2 + k];
        g_slot[t * 2 + k] = p;
    }
}

// -------------------- up GEMM: 256M x 64N (W1 & W3), K=HDIM --------------------
#define UP_AH  0
#define UP_AL  (256 * SROW)
#define UP_B1H (2 * 256 * SROW)
#define UP_B1L (UP_B1H + 64 * SROW)
#define UP_B3H (UP_B1L + 64 * SROW)
#define UP_B3L (UP_B3H + 64 * SROW)
#define UP_STAGE (UP_B3L + 64 * SROW)        // 61440 B
#define UP_SMEM  (3 * UP_STAGE)              // 184320 B

__global__ __launch_bounds__(256, 1) void up_mm() {
    int e    = blockIdx.z;
    int mEnd = g_off[e + 1];
    int m0   = g_off[e] + blockIdx.y * 256;
    if (m0 >= mEnd) return;
    int n0 = blockIdx.x * 64;

    extern __shared__ char smem[];
    uint32_t sb = smem_u32(smem);
    int tid = threadIdx.x, lane = tid & 31, wid = tid >> 5;

    // ---- loader setup: thread row r (0..63) covers rows r+64q, seg = 16B quarter ----
    int r = tid >> 2, seg = tid & 3;
    bool  va[4]; int tok[4];
#pragma unroll
    for (int q = 0; q < 4; q++) {
        int slot = m0 + r + 64 * q;
        va[q]  = slot < mEnd;
        tok[q] = va[q] ? g_perm[slot] : 0;
    }
    size_t browo = ((size_t)e * FFN + n0 + r) * HDIM + seg * 8;
    const __nv_bfloat16* b1h = g_w1_hi + browo;
    const __nv_bfloat16* b1l = g_w1_lo + browo;
    const __nv_bfloat16* b3h = g_w3_hi + browo;
    const __nv_bfloat16* b3l = g_w3_lo + browo;

#define UP_LOAD(st, kb) do {                                                    \
        uint32_t o_ = sb + (st) * UP_STAGE;                                     \
        _Pragma("unroll")                                                       \
        for (int q = 0; q < 4; q++) {                                           \
            uint32_t d_ = o_ + (r + 64 * q) * SROW + seg * 16;                  \
            const __nv_bfloat16* sh = g_x_hi + (size_t)tok[q] * HDIM + seg * 8 + (kb); \
            const __nv_bfloat16* sl = g_x_lo + (size_t)tok[q] * HDIM + seg * 8 + (kb); \
            cpa16(d_ + UP_AH, sh, va[q]);                                       \
            cpa16(d_ + UP_AL, sl, va[q]);                                       \
        }                                                                       \
        uint32_t db_ = o_ + r * SROW + seg * 16;                                \
        cpa16(db_ + UP_B1H, b1h + (kb), true);                                  \
        cpa16(db_ + UP_B1L, b1l + (kb), true);                                  \
        cpa16(db_ + UP_B3H, b3h + (kb), true);                                  \
        cpa16(db_ + UP_B3L, b3l + (kb), true);                                  \
        CP_COMMIT();                                                            \
    } while (0)

    // ---- compute setup: warp = (wid&3) M-quarter of 64 rows, (wid>>2) N-half of 32 ----
    int warpM = wid & 3, warpN = wid >> 2;
    uint32_t aOff = (uint32_t)((lane & 15) * SROW + (lane >> 4) * 16);
    uint32_t bOff = (uint32_t)(((lane & 7) + ((lane >> 4) << 3)) * SROW + ((lane >> 3) & 1) * 16);

    float acc1[4][4][4], acc3[4][4][4];
#pragma unroll
    for (int i = 0; i < 4; i++)
#pragma unroll
        for (int j = 0; j < 4; j++)
#pragma unroll
            for (int q = 0; q < 4; q++) { acc1[i][j][q] = 0.f; acc3[i][j][q] = 0.f; }

    UP_LOAD(0, 0);
    UP_LOAD(1, 32);
    const int NCH = HDIM / 32;
#pragma unroll 1
    for (int c = 0; c < NCH; c++) {
        int buf = c % 3;
        if (c + 2 < NCH) UP_LOAD((c + 2) % 3, (c + 2) * 32);
        else CP_COMMIT();
        CP_WAIT2();
        __syncthreads();

        uint32_t s0  = sb + buf * UP_STAGE;
        uint32_t aH  = s0 + UP_AH  + (warpM * 64) * SROW + aOff;
        uint32_t aL  = s0 + UP_AL  + (warpM * 64) * SROW + aOff;
        uint32_t b1H = s0 + UP_B1H + (warpN * 32) * SROW + bOff;
        uint32_t b1L = s0 + UP_B1L + (warpN * 32) * SROW + bOff;
        uint32_t b3H = s0 + UP_B3H + (warpN * 32) * SROW + bOff;
        uint32_t b3L = s0 + UP_B3L + (warpN * 32) * SROW + bOff;

#pragma unroll
        for (int ks = 0; ks < 2; ks++) {
            uint32_t ah[4][4], al[4][4];
#pragma unroll
            for (int i = 0; i < 4; i++) {
                LDM4(ah[i], aH + i * 16 * SROW + ks * 32);
                LDM4(al[i], aL + i * 16 * SROW + ks * 32);
            }
#pragma unroll
            for (int jp = 0; jp < 2; jp++) {
                uint32_t bh[4], bl[4];
                LDM4(bh, b1H + jp * 16 * SROW + ks * 32);
                LDM4(bl, b1L + jp * 16 * SROW + ks * 32);
#pragma unroll
                for (int i = 0; i < 4; i++) {
                    MMA(acc1[i][2 * jp],     ah[i], bh[0], bh[1]);
                    MMA(acc1[i][2 * jp],     ah[i], bl[0], bl[1]);
                    MMA(acc1[i][2 * jp],     al[i], bh[0], bh[1]);
                    MMA(acc1[i][2 * jp + 1], ah[i], bh[2], bh[3]);
                    MMA(acc1[i][2 * jp + 1], ah[i], bl[2], bl[3]);
                    MMA(acc1[i][2 * jp + 1], al[i], bh[2], bh[3]);
                }
            }
#pragma unroll
            for (int jp = 0; jp < 2; jp++) {
                uint32_t bh[4], bl[4];
                LDM4(bh, b3H + jp * 16 * SROW + ks * 32);
                LDM4(bl, b3L + jp * 16 * SROW + ks * 32);
#pragma unroll
                for (int i = 0; i < 4; i++) {
                    MMA(acc3[i][2 * jp],     ah[i], bh[0], bh[1]);
                    MMA(acc3[i][2 * jp],     ah[i], bl[0], bl[1]);
                    MMA(acc3[i][2 * jp],     al[i], bh[0], bh[1]);
                    MMA(acc3[i][2 * jp + 1], ah[i], bh[2], bh[3]);
                    MMA(acc3[i][2 * jp + 1], ah[i], bl[2], bl[3]);
                    MMA(acc3[i][2 * jp + 1], al[i], bh[2], bh[3]);
                }
            }
        }
        __syncthreads();
    }

    // ---- epilogue: SwiGLU * weight -> G hi/lo ----
#pragma unroll
    for (int i = 0; i < 4; i++) {
#pragma unroll
        for (int h = 0; h < 2; h++) {
            int rloc = warpM * 64 + i * 16 + (lane >> 2) + h * 8;
            int slot = m0 + rloc;
            if (slot < mEnd) {
                float w = g_permw[slot];
                size_t rowoff = (size_t)slot * FFN;
#pragma unroll
                for (int j = 0; j < 4; j++) {
                    float d1a = acc1[i][j][2 * h], d1b = acc1[i][j][2 * h + 1];
                    float d3a = acc3[i][j][2 * h], d3b = acc3[i][j][2 * h + 1];
                    float ga = d1a / (1.f + expf(-d1a)) * d3a * w;
                    float gb = d1b / (1.f + expf(-d1b)) * d3b * w;
                    __nv_bfloat16 ha = __float2bfloat16(ga), hb = __float2bfloat16(gb);
                    __nv_bfloat16 la = __float2bfloat16(ga - __bfloat162float(ha));
                    __nv_bfloat16 lb = __float2bfloat16(gb - __bfloat162float(hb));
                    int cc = n0 + warpN * 32 + j * 8 + (lane & 3) * 2;
                    *(__nv_bfloat162*)(g_G_hi + rowoff + cc) = __halves2bfloat162(ha, hb);
                    *(__nv_bfloat162*)(g_G_lo + rowoff + cc) = __halves2bfloat162(la, lb);
                }
            }
        }
    }
#undef UP_LOAD
}

// -------------------- down GEMM: 256M x 128N, K=FFN --------------------
#define DN_AH  0
#define DN_AL  (256 * SROW)
#define DN_BH  (2 * 256 * SROW)
#define DN_BL  (DN_BH + 128 * SROW)
#define DN_STAGE (DN_BL + 128 * SROW)        // 61440 B
#define DN_SMEM  (3 * DN_STAGE)

__global__ __launch_bounds__(256, 1) void down_mm() {
    int e    = blockIdx.z;
    int mEnd = g_off[e + 1];
    int m0   = g_off[e] + blockIdx.y * 256;
    if (m0 >= mEnd) return;
    int n0 = blockIdx.x * 128;

    extern __shared__ char smem[];
    uint32_t sb = smem_u32(smem);
    int tid = threadIdx.x, lane = tid & 31, wid = tid >> 5;

    int r = tid >> 2, seg = tid & 3;
    bool va[4]; int srow[4];
#pragma unroll
    for (int q = 0; q < 4; q++) {
        int slot = m0 + r + 64 * q;
        va[q]   = slot < mEnd;
        srow[q] = va[q] ? slot : 0;
    }
    size_t brow0 = ((size_t)e * HDIM + n0 + r) * FFN + seg * 8;
    size_t brow1 = ((size_t)e * HDIM + n0 + r + 64) * FFN + seg * 8;
    const __nv_bfloat16* bh0 = g_w2_hi + brow0;
    const __nv_bfloat16* bh1 = g_w2_hi + brow1;
    const __nv_bfloat16* bl0 = g_w2_lo + brow0;
    const __nv_bfloat16* bl1 = g_w2_lo + brow1;

#define DN_LOAD(st, kb) do {                                                    \
        uint32_t o_ = sb + (st) * DN_STAGE;                                     \
        _Pragma("unroll")                                                       \
        for (int q = 0; q < 4; q++) {                                           \
            uint32_t d_ = o_ + (r + 64 * q) * SROW + seg * 16;                  \
            const __nv_bfloat16* sh = g_G_hi + (size_t)srow[q] * FFN + seg * 8 + (kb); \
            const __nv_bfloat16* sl = g_G_lo + (size_t)srow[q] * FFN + seg * 8 + (kb); \
            cpa16(d_ + DN_AH, sh, va[q]);                                       \
            cpa16(d_ + DN_AL, sl, va[q]);                                       \
        }                                                                       \
        uint32_t db0 = o_ + r * SROW + seg * 16;                                \
        uint32_t db1 = o_ + (r + 64) * SROW + seg * 16;                         \
        cpa16(db0 + DN_BH, bh0 + (kb), true);                                   \
        cpa16(db1 + DN_BH, bh1 + (kb), true);                                   \
        cpa16(db0 + DN_BL, bl0 + (kb), true);                                   \
        cpa16(db1 + DN_BL, bl1 + (kb), true);                                   \
        CP_COMMIT();                                                            \
    } while (0)

    int warpM = wid & 3, warpN = wid >> 2;
    uint32_t aOff = (uint32_t)((lane & 15) * SROW + (lane >> 4) * 16);
    uint32_t bOff = (uint32_t)(((lane & 7) + ((lane >> 4) << 3)) * SROW + ((lane >> 3) & 1) * 16);

    float acc[4][8][4];
#pragma unroll
    for (int i = 0; i < 4; i++)
#pragma unroll
        for (int j = 0; j < 8; j++)
#pragma unroll
            for (int q = 0; q < 4; q++) acc[i][j][q] = 0.f;

    DN_LOAD(0, 0);
    DN_LOAD(1, 32);
    const int NCH = FFN / 32;
#pragma unroll 1
    for (int c = 0; c < NCH; c++) {
        int buf = c % 3;
        if (c + 2 < NCH) DN_LOAD((c + 2) % 3, (c + 2) * 32);
        else CP_COMMIT();
        CP_WAIT2();
        __syncthreads();

        uint32_t s0 = sb + buf * DN_STAGE;
        uint32_t aH = s0 + DN_AH + (warpM * 64) * SROW + aOff;
        uint32_t aL = s0 + DN_AL + (warpM * 64) * SROW + aOff;
        uint32_t bH = s0 + DN_BH + (warpN * 64) * SROW + bOff;
        uint32_t bL = s0 + DN_BL + (warpN * 64) * SROW + bOff;

#pragma unroll
        for (int ks = 0; ks < 2; ks++) {
            uint32_t ah[4][4], al[4][4];
#pragma unroll
            for (int i = 0; i < 4; i++) {
                LDM4(ah[i], aH + i * 16 * SROW + ks * 32);
                LDM4(al[i], aL + i * 16 * SROW + ks * 32);
            }
#pragma unroll
            for (int jp = 0; jp < 4; jp++) {
                uint32_t bh[4], bl[4];
                LDM4(bh, bH + jp * 16 * SROW + ks * 32);
                LDM4(bl, bL + jp * 16 * SROW + ks * 32);
#pragma unroll
                for (int i = 0; i < 4; i++) {
                    MMA(acc[i][2 * jp],     ah[i], bh[0], bh[1]);
                    MMA(acc[i][2 * jp],     ah[i], bl[0], bl[1]);
                    MMA(acc[i][2 * jp],     al[i], bh[0], bh[1]);
                    MMA(acc[i][2 * jp + 1], ah[i], bh[2], bh[3]);
                    MMA(acc[i][2 * jp + 1], ah[i], bl[2], bl[3]);
                    MMA(acc[i][2 * jp + 1], al[i], bh[2], bh[3]);
                }
            }
        }
        __syncthreads();
    }

#pragma unroll
    for (int i = 0; i < 4; i++) {
#pragma unroll
        for (int h = 0; h < 2; h++) {
            int rloc = warpM * 64 + i * 16 + (lane >> 2) + h * 8;
            int slot = m0 + rloc;
            if (slot < mEnd) {
                float* yrow = g_Y + (size_t)slot * HDIM;
#pragma unroll
                for (int j = 0; j < 8; j++) {
                    int cc = n0 + warpN * 64 + j * 8 + (lane & 3) * 2;
                    *(float2*)(yrow + cc) =
                        make_float2(acc[i][j][2 * h], acc[i][j][2 * h + 1]);
                }
            }
        }
    }
#undef DN_LOAD
}

// -------------------- combine --------------------
__global__ void combine_kernel(float* __restrict__ out) {
    int idx = blockIdx.x * blockDim.x + threadIdx.x;
    if (idx >= T * (HDIM / 4)) return;
    int t  = idx / (HDIM / 4);
    int hq = idx % (HDIM / 4);
    int s0 = g_slot[t * 2 + 0];
    int s1 = g_slot[t * 2 + 1];
    float4 a = *(const float4*)&g_Y[(size_t)s0 * HDIM + hq * 4];
    float4 b = *(const float4*)&g_Y[(size_t)s1 * HDIM + hq * 4];
    *(float4*)&out[(size_t)t * HDIM + hq * 4] =
        make_float4(a.x + b.x, a.y + b.y, a.z + b.z, a.w + b.w);
}

// -------------------- launcher --------------------
extern "C" void kernel_launch(void* const* d_in, const int* in_sizes, int n_in,
                              void* d_out, int out_size) {
    const float* x    = (const float*)d_in[0];
    const float* Wg   = (const float*)d_in[1];
    const float* W1   = (const float*)d_in[2];
    const float* W2   = (const float*)d_in[3];
    const float* W3   = (const float*)d_in[4];
    const float* bias = (const float*)d_in[5];
    float* out = (float*)d_out;

    cudaFuncSetAttribute(up_mm,   cudaFuncAttributeMaxDynamicSharedMemorySize, UP_SMEM);
    cudaFuncSetAttribute(down_mm, cudaFuncAttributeMaxDynamicSharedMemorySize, DN_SMEM);

    // launch order arranged so ncu (-s 5 -c 1) captures up_mm
    init_kernel<<<1, 32>>>();                                   // 0
    {
        size_t nx = (size_t)T * HDIM / 4, nw = (size_t)NEXP * FFN * HDIM / 4;
        size_t total = nx + 3 * nw;
        convert_all<<<(unsigned)((total + 255) / 256), 256>>>(x, W1, W3, W2);  // 1
    }
    router_kernel<<<T / 8, 256>>>(x, Wg, bias);                 // 2
    offsets_kernel<<<1, 32>>>();                                // 3
    scatter_kernel<<<(T + 255) / 256, 256>>>();                 // 4

    dim3 upGrid(FFN / 64, T / 256, NEXP);
    up_mm<<<upGrid, 256, UP_SMEM>>>();                          // 5 (profiled)

    dim3 dnGrid(HDIM / 128, T / 256, NEXP);
    down_mm<<<dnGrid, 256, DN_SMEM>>>();                        // 6

    combine_kernel<<<(T * (HDIM / 4) + 255) / 256, 256>>>(out); // 7
}

// round 5
// speedup vs baseline: 3.2271x; 1.3698x over previous
#include <cuda_runtime.h>
#include <cuda_fp16.h>
#include <math.h>
#include <stdint.h>

// -------------------- problem constants --------------------
#define T      4096
#define HDIM   2048
#define FFN    1024
#define NEXP   8
#define TOPK   2
#define SLOTS  (T * TOPK)

// -------------------- scratch (device globals; no allocs) --------------------
__device__ int   g_topk_idx[T * TOPK];
__device__ float g_topk_w[T * TOPK];
__device__ int   g_cnt[NEXP];
__device__ int   g_cur[NEXP];
__device__ int   g_off[NEXP + 1];
__device__ int   g_perm[SLOTS];
__device__ float g_permw[SLOTS];
__device__ int   g_slot[T * TOPK];

__device__ __half g_x   [(size_t)T * HDIM];
__device__ __half g_w1_h[(size_t)NEXP * FFN * HDIM];
__device__ __half g_w1_l[(size_t)NEXP * FFN * HDIM];
__device__ __half g_w3_h[(size_t)NEXP * FFN * HDIM];
__device__ __half g_w3_l[(size_t)NEXP * FFN * HDIM];
__device__ __half g_w2_h[(size_t)NEXP * HDIM * FFN];
__device__ __half g_w2_l[(size_t)NEXP * HDIM * FFN];
__device__ __half g_G   [(size_t)SLOTS * FFN];
__device__ float  g_Y   [(size_t)SLOTS * HDIM];

// -------------------- helpers --------------------
__device__ __forceinline__ uint32_t smem_u32(const void* p) {
    uint32_t a;
    asm("{ .reg .u64 t; cvta.to.shared.u64 t, %1; cvt.u32.u64 %0, t; }" : "=r"(a) : "l"(p));
    return a;
}
__device__ __forceinline__ void cpa16(uint32_t dst, const void* src, bool v) {
    uint64_t g = __cvta_generic_to_global(src);
    int sz = v ? 16 : 0;
    asm volatile("cp.async.cg.shared.global [%0], [%1], 16, %2;"
                 :: "r"(dst), "l"(g), "r"(sz) : "memory");
}
#define CP_COMMIT() asm volatile("cp.async.commit_group;" ::: "memory")
#define CP_WAIT2()  asm volatile("cp.async.wait_group 2;" ::: "memory")

#define LDM4(r, a) \
    asm volatile("ldmatrix.sync.aligned.m8n8.x4.shared.b16 {%0,%1,%2,%3}, [%4];" \
        : "=r"((r)[0]), "=r"((r)[1]), "=r"((r)[2]), "=r"((r)[3]) : "r"(a))

#define MMAH(d, a, b0, b1) \
    asm volatile("mma.sync.aligned.m16n8k16.row.col.f32.f16.f16.f32 " \
        "{%0,%1,%2,%3},{%4,%5,%6,%7},{%8,%9},{%0,%1,%2,%3};" \
        : "+f"((d)[0]), "+f"((d)[1]), "+f"((d)[2]), "+f"((d)[3]) \
        : "r"((a)[0]), "r"((a)[1]), "r"((a)[2]), "r"((a)[3]), "r"(b0), "r"(b1))

// smem row stride: 32 fp16 data (64B) + 16B pad = 80 bytes (conflict-free ldmatrix)
#define SROW 80

// -------------------- init --------------------
__global__ void init_kernel() {
    int i = threadIdx.x;
    if (i < NEXP) { g_cnt[i] = 0; g_cur[i] = 0; }
}

// -------------------- fused conversion: x -> fp16; W1/W3/W2 -> fp16 hi/lo ----
__global__ void convert_all(const float* __restrict__ x, const float* __restrict__ W1,
                            const float* __restrict__ W3, const float* __restrict__ W2) {
    const size_t nx = (size_t)T * HDIM / 4;
    const size_t nw = (size_t)NEXP * FFN * HDIM / 4;
    size_t i = (size_t)blockIdx.x * blockDim.x + threadIdx.x;
    if (i < nx) {
        float4 v = ((const float4*)x)[i];
        ((__half2*)g_x)[i * 2 + 0] = __halves2half2(__float2half(v.x), __float2half(v.y));
        ((__half2*)g_x)[i * 2 + 1] = __halves2half2(__float2half(v.z), __float2half(v.w));
        return;
    }
    const float* s; __half *hi, *lo; size_t j;
    if (i < nx + nw)          { s = W1; hi = g_w1_h; lo = g_w1_l; j = i - nx; }
    else if (i < nx + 2 * nw) { s = W3; hi = g_w3_h; lo = g_w3_l; j = i - nx - nw; }
    else if (i < nx + 3 * nw) { s = W2; hi = g_w2_h; lo = g_w2_l; j = i - nx - 2 * nw; }
    else return;
    float4 v = ((const float4*)s)[j];
    __half h0 = __float2half(v.x), h1 = __float2half(v.y);
    __half h2 = __float2half(v.z), h3 = __float2half(v.w);
    __half l0 = __float2half(v.x - __half2float(h0));
    __half l1 = __float2half(v.y - __half2float(h1));
    __half l2 = __float2half(v.z - __half2float(h2));
    __half l3 = __float2half(v.w - __half2float(h3));
    ((__half2*)hi)[j * 2 + 0] = __halves2half2(h0, h1);
    ((__half2*)hi)[j * 2 + 1] = __halves2half2(h2, h3);
    ((__half2*)lo)[j * 2 + 0] = __halves2half2(l0, l1);
    ((__half2*)lo)[j * 2 + 1] = __halves2half2(l2, l3);
}

// -------------------- router --------------------
__global__ void router_kernel(const float* __restrict__ x,
                              const float* __restrict__ Wg,
                              const float* __restrict__ bias) {
    int gw   = (blockIdx.x * blockDim.x + threadIdx.x) >> 5;
    int lane = threadIdx.x & 31;
    if (gw >= T) return;
    const float* xr = x + (size_t)gw * HDIM;
    float acc[NEXP];
#pragma unroll
    for (int e = 0; e < NEXP; e++) acc[e] = 0.f;
    for (int k = lane * 4; k < HDIM; k += 32 * 4) {
        float4 xv = *(const float4*)(xr + k);
#pragma unroll
        for (int e = 0; e < NEXP; e++) {
            float4 wv = *(const float4*)(Wg + (size_t)e * HDIM + k);
            acc[e] += xv.x * wv.x + xv.y * wv.y + xv.z * wv.z + xv.w * wv.w;
        }
    }
#pragma unroll
    for (int e = 0; e < NEXP; e++) {
#pragma unroll
        for (int o = 16; o > 0; o >>= 1)
            acc[e] += __shfl_xor_sync(0xFFFFFFFFu, acc[e], o);
    }
    if (lane == 0) {
        float rw[NEXP], sc[NEXP];
#pragma unroll
        for (int e = 0; e < NEXP; e++) {
            rw[e] = 1.f / (1.f + expf(-acc[e]));
            sc[e] = rw[e] + bias[e];
        }
        int i0 = 0; float s0 = sc[0];
#pragma unroll
        for (int e = 1; e < NEXP; e++) if (sc[e] > s0) { s0 = sc[e]; i0 = e; }
        int i1 = -1; float s1 = -1e30f;
#pragma unroll
        for (int e = 0; e < NEXP; e++) {
            if (e == i0) continue;
            if (sc[e] > s1) { s1 = sc[e]; i1 = e; }
        }
        float wsum = rw[i0] + rw[i1];
        g_topk_idx[gw * 2 + 0] = i0;
        g_topk_idx[gw * 2 + 1] = i1;
        g_topk_w[gw * 2 + 0] = rw[i0] / wsum;
        g_topk_w[gw * 2 + 1] = rw[i1] / wsum;
        atomicAdd(&g_cnt[i0], 1);
        atomicAdd(&g_cnt[i1], 1);
    }
}

__global__ void offsets_kernel() {
    if (threadIdx.x == 0) {
        int acc = 0;
        g_off[0] = 0;
        for (int e = 0; e < NEXP; e++) { acc += g_cnt[e]; g_off[e + 1] = acc; }
    }
}

__global__ void scatter_kernel() {
    int t = blockIdx.x * blockDim.x + threadIdx.x;
    if (t >= T) return;
#pragma unroll
    for (int k = 0; k < TOPK; k++) {
        int e = g_topk_idx[t * 2 + k];
        int p = g_off[e] + atomicAdd(&g_cur[e], 1);
        g_perm[p]  = t;
        g_permw[p] = g_topk_w[t * 2 + k];
        g_slot[t * 2 + k] = p;
    }
}

// -------------------- up GEMM: 256M x 64N (W1 & W3), K=HDIM --------------------
// A single fp16; B1/B3 hi+lo fp16. 2-term MMA.
#define UP_A   0
#define UP_B1H (256 * SROW)
#define UP_B1L (UP_B1H + 64 * SROW)
#define UP_B3H (UP_B1L + 64 * SROW)
#define UP_B3L (UP_B3H + 64 * SROW)
#define UP_STAGE (UP_B3L + 64 * SROW)        // 40960 B
#define UP_SMEM  (3 * UP_STAGE)              // 122880 B

__global__ __launch_bounds__(256, 1) void up_mm() {
    int e    = blockIdx.z;
    int mEnd = g_off[e + 1];
    int m0   = g_off[e] + blockIdx.y * 256;
    if (m0 >= mEnd) return;
    int n0 = blockIdx.x * 64;

    extern __shared__ char smem[];
    uint32_t sb = smem_u32(smem);
    int tid = threadIdx.x, lane = tid & 31, wid = tid >> 5;

    // loader: thread row r (0..63) covers A rows r+64q; seg = 16B quarter of 64B chunk-row
    int r = tid >> 2, seg = tid & 3;
    bool  va[4]; int tok[4];
#pragma unroll
    for (int q = 0; q < 4; q++) {
        int slot = m0 + r + 64 * q;
        va[q]  = slot < mEnd;
        tok[q] = va[q] ? g_perm[slot] : 0;
    }
    size_t browo = ((size_t)e * FFN + n0 + r) * HDIM + seg * 8;
    const __half* b1h = g_w1_h + browo;
    const __half* b1l = g_w1_l + browo;
    const __half* b3h = g_w3_h + browo;
    const __half* b3l = g_w3_l + browo;

#define UP_LOAD(st, kb) do {                                                    \
        uint32_t o_ = sb + (st) * UP_STAGE;                                     \
        _Pragma("unroll")                                                       \
        for (int q = 0; q < 4; q++) {                                           \
            uint32_t d_ = o_ + UP_A + (r + 64 * q) * SROW + seg * 16;           \
            const __half* sa = g_x + (size_t)tok[q] * HDIM + seg * 8 + (kb);    \
            cpa16(d_, sa, va[q]);                                               \
        }                                                                       \
        uint32_t db_ = o_ + r * SROW + seg * 16;                                \
        cpa16(db_ + UP_B1H, b1h + (kb), true);                                  \
        cpa16(db_ + UP_B1L, b1l + (kb), true);                                  \
        cpa16(db_ + UP_B3H, b3h + (kb), true);                                  \
        cpa16(db_ + UP_B3L, b3l + (kb), true);                                  \
        CP_COMMIT();                                                            \
    } while (0)

    int warpM = wid & 3, warpN = wid >> 2;
    uint32_t aOff = (uint32_t)((lane & 15) * SROW + (lane >> 4) * 16);
    uint32_t bOff = (uint32_t)(((lane & 7) + ((lane >> 4) << 3)) * SROW + ((lane >> 3) & 1) * 16);

    float acc1[4][4][4], acc3[4][4][4];
#pragma unroll
    for (int i = 0; i < 4; i++)
#pragma unroll
        for (int j = 0; j < 4; j++)
#pragma unroll
            for (int q = 0; q < 4; q++) { acc1[i][j][q] = 0.f; acc3[i][j][q] = 0.f; }

    UP_LOAD(0, 0);
    UP_LOAD(1, 32);
    const int NCH = HDIM / 32;
#pragma unroll 1
    for (int c = 0; c < NCH; c++) {
        int buf = c % 3;
        if (c + 2 < NCH) UP_LOAD((c + 2) % 3, (c + 2) * 32);
        else CP_COMMIT();
        CP_WAIT2();
        __syncthreads();

        uint32_t s0  = sb + buf * UP_STAGE;
        uint32_t aA  = s0 + UP_A   + (warpM * 64) * SROW + aOff;
        uint32_t b1H = s0 + UP_B1H + (warpN * 32) * SROW + bOff;
        uint32_t b1L = s0 + UP_B1L + (warpN * 32) * SROW + bOff;
        uint32_t b3H = s0 + UP_B3H + (warpN * 32) * SROW + bOff;
        uint32_t b3L = s0 + UP_B3L + (warpN * 32) * SROW + bOff;

#pragma unroll
        for (int ks = 0; ks < 2; ks++) {
            uint32_t ah[4][4];
#pragma unroll
            for (int i = 0; i < 4; i++)
                LDM4(ah[i], aA + i * 16 * SROW + ks * 32);
#pragma unroll
            for (int jp = 0; jp < 2; jp++) {
                uint32_t bh[4], bl[4];
                LDM4(bh, b1H + jp * 16 * SROW + ks * 32);
                LDM4(bl, b1L + jp * 16 * SROW + ks * 32);
#pragma unroll
                for (int i = 0; i < 4; i++) {
                    MMAH(acc1[i][2 * jp],     ah[i], bh[0], bh[1]);
                    MMAH(acc1[i][2 * jp],     ah[i], bl[0], bl[1]);
                    MMAH(acc1[i][2 * jp + 1], ah[i], bh[2], bh[3]);
                    MMAH(acc1[i][2 * jp + 1], ah[i], bl[2], bl[3]);
                }
            }
#pragma unroll
            for (int jp = 0; jp < 2; jp++) {
                uint32_t bh[4], bl[4];
                LDM4(bh, b3H + jp * 16 * SROW + ks * 32);
                LDM4(bl, b3L + jp * 16 * SROW + ks * 32);
#pragma unroll
                for (int i = 0; i < 4; i++) {
                    MMAH(acc3[i][2 * jp],     ah[i], bh[0], bh[1]);
                    MMAH(acc3[i][2 * jp],     ah[i], bl[0], bl[1]);
                    MMAH(acc3[i][2 * jp + 1], ah[i], bh[2], bh[3]);
                    MMAH(acc3[i][2 * jp + 1], ah[i], bl[2], bl[3]);
                }
            }
        }
        __syncthreads();
    }

    // epilogue: SwiGLU * weight -> G (fp16)
#pragma unroll
    for (int i = 0; i < 4; i++) {
#pragma unroll
        for (int h = 0; h < 2; h++) {
            int rloc = warpM * 64 + i * 16 + (lane >> 2) + h * 8;
            int slot = m0 + rloc;
            if (slot < mEnd) {
                float w = g_permw[slot];
                size_t rowoff = (size_t)slot * FFN;
#pragma unroll
                for (int j = 0; j < 4; j++) {
                    float d1a = acc1[i][j][2 * h], d1b = acc1[i][j][2 * h + 1];
                    float d3a = acc3[i][j][2 * h], d3b = acc3[i][j][2 * h + 1];
                    float ga = d1a / (1.f + expf(-d1a)) * d3a * w;
                    float gb = d1b / (1.f + expf(-d1b)) * d3b * w;
                    int cc = n0 + warpN * 32 + j * 8 + (lane & 3) * 2;
                    *(__half2*)(g_G + rowoff + cc) =
                        __halves2half2(__float2half(ga), __float2half(gb));
                }
            }
        }
    }
#undef UP_LOAD
}

// -------------------- down GEMM: 256M x 128N, K=FFN --------------------
// A = G single fp16; B = W2 hi+lo. 2-term MMA.
#define DN_A   0
#define DN_BH  (256 * SROW)
#define DN_BL  (DN_BH + 128 * SROW)
#define DN_STAGE (DN_BL + 128 * SROW)        // 40960 B
#define DN_SMEM  (3 * DN_STAGE)

__global__ __launch_bounds__(256, 1) void down_mm() {
    int e    = blockIdx.z;
    int mEnd = g_off[e + 1];
    int m0   = g_off[e] + blockIdx.y * 256;
    if (m0 >= mEnd) return;
    int n0 = blockIdx.x * 128;

    extern __shared__ char smem[];
    uint32_t sb = smem_u32(smem);
    int tid = threadIdx.x, lane = tid & 31, wid = tid >> 5;

    int r = tid >> 2, seg = tid & 3;
    bool va[4]; int srow[4];
#pragma unroll
    for (int q = 0; q < 4; q++) {
        int slot = m0 + r + 64 * q;
        va[q]   = slot < mEnd;
        srow[q] = va[q] ? slot : 0;
    }
    size_t brow0 = ((size_t)e * HDIM + n0 + r) * FFN + seg * 8;
    size_t brow1 = ((size_t)e * HDIM + n0 + r + 64) * FFN + seg * 8;
    const __half* bh0 = g_w2_h + brow0;
    const __half* bh1 = g_w2_h + brow1;
    const __half* bl0 = g_w2_l + brow0;
    const __half* bl1 = g_w2_l + brow1;

#define DN_LOAD(st, kb) do {                                                    \
        uint32_t o_ = sb + (st) * DN_STAGE;                                     \
        _Pragma("unroll")                                                       \
        for (int q = 0; q < 4; q++) {                                           \
            uint32_t d_ = o_ + DN_A + (r + 64 * q) * SROW + seg * 16;           \
            const __half* sa = g_G + (size_t)srow[q] * FFN + seg * 8 + (kb);    \
            cpa16(d_, sa, va[q]);                                               \
        }                                                                       \
        uint32_t db0 = o_ + r * SROW + seg * 16;                                \
        uint32_t db1 = o_ + (r + 64) * SROW + seg * 16;                         \
        cpa16(db0 + DN_BH, bh0 + (kb), true);                                   \
        cpa16(db1 + DN_BH, bh1 + (kb), true);                                   \
        cpa16(db0 + DN_BL, bl0 + (kb), true);                                   \
        cpa16(db1 + DN_BL, bl1 + (kb), true);                                   \
        CP_COMMIT();                                                            \
    } while (0)

    int warpM = wid & 3, warpN = wid >> 2;
    uint32_t aOff = (uint32_t)((lane & 15) * SROW + (lane >> 4) * 16);
    uint32_t bOff = (uint32_t)(((lane & 7) + ((lane >> 4) << 3)) * SROW + ((lane >> 3) & 1) * 16);

    float acc[4][8][4];
#pragma unroll
    for (int i = 0; i < 4; i++)
#pragma unroll
        for (int j = 0; j < 8; j++)
#pragma unroll
            for (int q = 0; q < 4; q++) acc[i][j][q] = 0.f;

    DN_LOAD(0, 0);
    DN_LOAD(1, 32);
    const int NCH = FFN / 32;
#pragma unroll 1
    for (int c = 0; c < NCH; c++) {
        int buf = c % 3;
        if (c + 2 < NCH) DN_LOAD((c + 2) % 3, (c + 2) * 32);
        else CP_COMMIT();
        CP_WAIT2();
        __syncthreads();

        uint32_t s0 = sb + buf * DN_STAGE;
        uint32_t aA = s0 + DN_A  + (warpM * 64) * SROW + aOff;
        uint32_t bH = s0 + DN_BH + (warpN * 64) * SROW + bOff;
        uint32_t bL = s0 + DN_BL + (warpN * 64) * SROW + bOff;

#pragma unroll
        for (int ks = 0; ks < 2; ks++) {
            uint32_t ah[4][4];
#pragma unroll
            for (int i = 0; i < 4; i++)
                LDM4(ah[i], aA + i * 16 * SROW + ks * 32);
#pragma unroll
            for (int jp = 0; jp < 4; jp++) {
                uint32_t bh[4], bl[4];
                LDM4(bh, bH + jp * 16 * SROW + ks * 32);
                LDM4(bl, bL + jp * 16 * SROW + ks * 32);
#pragma unroll
                for (int i = 0; i < 4; i++) {
                    MMAH(acc[i][2 * jp],     ah[i], bh[0], bh[1]);
                    MMAH(acc[i][2 * jp],     ah[i], bl[0], bl[1]);
                    MMAH(acc[i][2 * jp + 1], ah[i], bh[2], bh[3]);
                    MMAH(acc[i][2 * jp + 1], ah[i], bl[2], bl[3]);
                }
            }
        }
        __syncthreads();
    }

#pragma unroll
    for (int i = 0; i < 4; i++) {
#pragma unroll
        for (int h = 0; h < 2; h++) {
            int rloc = warpM * 64 + i * 16 + (lane >> 2) + h * 8;
            int slot = m0 + rloc;
            if (slot < mEnd) {
                float* yrow = g_Y + (size_t)slot * HDIM;
#pragma unroll
                for (int j = 0; j < 8; j++) {
                    int cc = n0 + warpN * 64 + j * 8 + (lane & 3) * 2;
                    *(float2*)(yrow + cc) =
                        make_float2(acc[i][j][2 * h], acc[i][j][2 * h + 1]);
                }
            }
        }
    }
#undef DN_LOAD
}

// -------------------- combine --------------------
__global__ void combine_kernel(float* __restrict__ out) {
    int idx = blockIdx.x * blockDim.x + threadIdx.x;
    if (idx >= T * (HDIM / 4)) return;
    int t  = idx / (HDIM / 4);
    int hq = idx % (HDIM / 4);
    int s0 = g_slot[t * 2 + 0];
    int s1 = g_slot[t * 2 + 1];
    float4 a = *(const float4*)&g_Y[(size_t)s0 * HDIM + hq * 4];
    float4 b = *(const float4*)&g_Y[(size_t)s1 * HDIM + hq * 4];
    *(float4*)&out[(size_t)t * HDIM + hq * 4] =
        make_float4(a.x + b.x, a.y + b.y, a.z + b.z, a.w + b.w);
}

// -------------------- launcher --------------------
extern "C" void kernel_launch(void* const* d_in, const int* in_sizes, int n_in,
                              void* d_out, int out_size) {
    const float* x    = (const float*)d_in[0];
    const float* Wg   = (const float*)d_in[1];
    const float* W1   = (const float*)d_in[2];
    const float* W2   = (const float*)d_in[3];
    const float* W3   = (const float*)d_in[4];
    const float* bias = (const float*)d_in[5];
    float* out = (float*)d_out;

    cudaFuncSetAttribute(up_mm,   cudaFuncAttributeMaxDynamicSharedMemorySize, UP_SMEM);
    cudaFuncSetAttribute(down_mm, cudaFuncAttributeMaxDynamicSharedMemorySize, DN_SMEM);

    init_kernel<<<1, 32>>>();                                   // 0
    {
        size_t nx = (size_t)T * HDIM / 4, nw = (size_t)NEXP * FFN * HDIM / 4;
        size_t total = nx + 3 * nw;
        convert_all<<<(unsigned)((total + 255) / 256), 256>>>(x, W1, W3, W2);  // 1
    }
    router_kernel<<<T / 8, 256>>>(x, Wg, bias);                 // 2
    offsets_kernel<<<1, 32>>>();                                // 3
    scatter_kernel<<<(T + 255) / 256, 256>>>();                 // 4

    dim3 upGrid(FFN / 64, T / 256, NEXP);
    up_mm<<<upGrid, 256, UP_SMEM>>>();                          // 5

    dim3 dnGrid(HDIM / 128, T / 256, NEXP);
    down_mm<<<dnGrid, 256, DN_SMEM>>>();                        // 6

    combine_kernel<<<(T * (HDIM / 4) + 255) / 256, 256>>>(out); // 7
}

// round 6
// speedup vs baseline: 4.6991x; 1.4561x over previous
#include <cuda_runtime.h>
#include <cuda_fp16.h>
#include <math.h>
#include <stdint.h>

// -------------------- problem constants --------------------
#define T      4096
#define HDIM   2048
#define FFN    1024
#define NEXP   8
#define TOPK   2
#define SLOTS  (T * TOPK)

// -------------------- scratch (device globals; no allocs) --------------------
__device__ int   g_topk_idx[T * TOPK];
__device__ float g_topk_w[T * TOPK];
__device__ int   g_cnt[NEXP];
__device__ int   g_cur[NEXP];
__device__ int   g_off[NEXP + 1];
__device__ int   g_perm[SLOTS];
__device__ float g_permw[SLOTS];
__device__ int   g_slot[T * TOPK];

__device__ __half g_x [(size_t)T * HDIM];
__device__ __half g_w1[(size_t)NEXP * FFN * HDIM];
__device__ __half g_w3[(size_t)NEXP * FFN * HDIM];
__device__ __half g_w2[(size_t)NEXP * HDIM * FFN];
__device__ __half g_G [(size_t)SLOTS * FFN];
__device__ float  g_Y [(size_t)SLOTS * HDIM];

// -------------------- helpers --------------------
__device__ __forceinline__ uint32_t smem_u32(const void* p) {
    uint32_t a;
    asm("{ .reg .u64 t; cvta.to.shared.u64 t, %1; cvt.u32.u64 %0, t; }" : "=r"(a) : "l"(p));
    return a;
}
__device__ __forceinline__ void cpa16(uint32_t dst, const void* src, bool v) {
    uint64_t g = __cvta_generic_to_global(src);
    int sz = v ? 16 : 0;
    asm volatile("cp.async.cg.shared.global [%0], [%1], 16, %2;"
                 :: "r"(dst), "l"(g), "r"(sz) : "memory");
}
#define CP_COMMIT() asm volatile("cp.async.commit_group;" ::: "memory")
#define CP_WAIT2()  asm volatile("cp.async.wait_group 2;" ::: "memory")

#define LDM4(r, a) \
    asm volatile("ldmatrix.sync.aligned.m8n8.x4.shared.b16 {%0,%1,%2,%3}, [%4];" \
        : "=r"((r)[0]), "=r"((r)[1]), "=r"((r)[2]), "=r"((r)[3]) : "r"(a))

#define MMAH(d, a, b0, b1) \
    asm volatile("mma.sync.aligned.m16n8k16.row.col.f32.f16.f16.f32 " \
        "{%0,%1,%2,%3},{%4,%5,%6,%7},{%8,%9},{%0,%1,%2,%3};" \
        : "+f"((d)[0]), "+f"((d)[1]), "+f"((d)[2]), "+f"((d)[3]) \
        : "r"((a)[0]), "r"((a)[1]), "r"((a)[2]), "r"((a)[3]), "r"(b0), "r"(b1))

// smem row stride: 32 fp16 (64B) + 16B pad = 80 B (conflict-free ldmatrix)
#define SROW 80

// -------------------- init --------------------
__global__ void init_kernel() {
    int i = threadIdx.x;
    if (i < NEXP) { g_cnt[i] = 0; g_cur[i] = 0; }
}

// -------------------- fused conversion: fp32 -> fp16 --------------------
__global__ void convert_all(const float* __restrict__ x, const float* __restrict__ W1,
                            const float* __restrict__ W3, const float* __restrict__ W2) {
    const size_t nx = (size_t)T * HDIM / 4;
    const size_t nw = (size_t)NEXP * FFN * HDIM / 4;
    size_t i = (size_t)blockIdx.x * blockDim.x + threadIdx.x;
    const float* s; __half* d; size_t j;
    if (i < nx)               { s = x;  d = g_x;  j = i; }
    else if (i < nx + nw)     { s = W1; d = g_w1; j = i - nx; }
    else if (i < nx + 2 * nw) { s = W3; d = g_w3; j = i - nx - nw; }
    else if (i < nx + 3 * nw) { s = W2; d = g_w2; j = i - nx - 2 * nw; }
    else return;
    float4 v = ((const float4*)s)[j];
    ((__half2*)d)[j * 2 + 0] = __halves2half2(__float2half(v.x), __float2half(v.y));
    ((__half2*)d)[j * 2 + 1] = __halves2half2(__float2half(v.z), __float2half(v.w));
}

// -------------------- router --------------------
__global__ void router_kernel(const float* __restrict__ x,
                              const float* __restrict__ Wg,
                              const float* __restrict__ bias) {
    int gw   = (blockIdx.x * blockDim.x + threadIdx.x) >> 5;
    int lane = threadIdx.x & 31;
    if (gw >= T) return;
    const float* xr = x + (size_t)gw * HDIM;
    float acc[NEXP];
#pragma unroll
    for (int e = 0; e < NEXP; e++) acc[e] = 0.f;
    for (int k = lane * 4; k < HDIM; k += 32 * 4) {
        float4 xv = *(const float4*)(xr + k);
#pragma unroll
        for (int e = 0; e < NEXP; e++) {
            float4 wv = *(const float4*)(Wg + (size_t)e * HDIM + k);
            acc[e] += xv.x * wv.x + xv.y * wv.y + xv.z * wv.z + xv.w * wv.w;
        }
    }
#pragma unroll
    for (int e = 0; e < NEXP; e++) {
#pragma unroll
        for (int o = 16; o > 0; o >>= 1)
            acc[e] += __shfl_xor_sync(0xFFFFFFFFu, acc[e], o);
    }
    if (lane == 0) {
        float rw[NEXP], sc[NEXP];
#pragma unroll
        for (int e = 0; e < NEXP; e++) {
            rw[e] = 1.f / (1.f + expf(-acc[e]));
            sc[e] = rw[e] + bias[e];
        }
        int i0 = 0; float s0 = sc[0];
#pragma unroll
        for (int e = 1; e < NEXP; e++) if (sc[e] > s0) { s0 = sc[e]; i0 = e; }
        int i1 = -1; float s1 = -1e30f;
#pragma unroll
        for (int e = 0; e < NEXP; e++) {
            if (e == i0) continue;
            if (sc[e] > s1) { s1 = sc[e]; i1 = e; }
        }
        float wsum = rw[i0] + rw[i1];
        g_topk_idx[gw * 2 + 0] = i0;
        g_topk_idx[gw * 2 + 1] = i1;
        g_topk_w[gw * 2 + 0] = rw[i0] / wsum;
        g_topk_w[gw * 2 + 1] = rw[i1] / wsum;
        atomicAdd(&g_cnt[i0], 1);
        atomicAdd(&g_cnt[i1], 1);
    }
}

__global__ void offsets_kernel() {
    if (threadIdx.x == 0) {
        int acc = 0;
        g_off[0] = 0;
        for (int e = 0; e < NEXP; e++) { acc += g_cnt[e]; g_off[e + 1] = acc; }
    }
}

__global__ void scatter_kernel() {
    int t = blockIdx.x * blockDim.x + threadIdx.x;
    if (t >= T) return;
#pragma unroll
    for (int k = 0; k < TOPK; k++) {
        int e = g_topk_idx[t * 2 + k];
        int p = g_off[e] + atomicAdd(&g_cur[e], 1);
        g_perm[p]  = t;
        g_permw[p] = g_topk_w[t * 2 + k];
        g_slot[t * 2 + k] = p;
    }
}

// -------------------- up GEMM: 256M x 64N (W1 & W3), K=HDIM, pure fp16 ------
#define UP_A   0
#define UP_B1  (256 * SROW)
#define UP_B3  (UP_B1 + 64 * SROW)
#define UP_STAGE (UP_B3 + 64 * SROW)         // 30720 B
#define UP_SMEM  (3 * UP_STAGE)              // 92160 B

__global__ __launch_bounds__(256, 1) void up_mm() {
    int e    = blockIdx.z;
    int mEnd = g_off[e + 1];
    int m0   = g_off[e] + blockIdx.y * 256;
    if (m0 >= mEnd) return;
    int n0 = blockIdx.x * 64;

    extern __shared__ char smem[];
    uint32_t sb = smem_u32(smem);
    int tid = threadIdx.x, lane = tid & 31, wid = tid >> 5;

    int r = tid >> 2, seg = tid & 3;
    bool  va[4]; int tok[4];
#pragma unroll
    for (int q = 0; q < 4; q++) {
        int slot = m0 + r + 64 * q;
        va[q]  = slot < mEnd;
        tok[q] = va[q] ? g_perm[slot] : 0;
    }
    size_t browo = ((size_t)e * FFN + n0 + r) * HDIM + seg * 8;
    const __half* b1p = g_w1 + browo;
    const __half* b3p = g_w3 + browo;

#define UP_LOAD(st, kb) do {                                                    \
        uint32_t o_ = sb + (st) * UP_STAGE;                                     \
        _Pragma("unroll")                                                       \
        for (int q = 0; q < 4; q++) {                                           \
            uint32_t d_ = o_ + UP_A + (r + 64 * q) * SROW + seg * 16;           \
            const __half* sa = g_x + (size_t)tok[q] * HDIM + seg * 8 + (kb);    \
            cpa16(d_, sa, va[q]);                                               \
        }                                                                       \
        uint32_t db_ = o_ + r * SROW + seg * 16;                                \
        cpa16(db_ + UP_B1, b1p + (kb), true);                                   \
        cpa16(db_ + UP_B3, b3p + (kb), true);                                   \
        CP_COMMIT();                                                            \
    } while (0)

    int warpM = wid & 3, warpN = wid >> 2;
    uint32_t aOff = (uint32_t)((lane & 15) * SROW + (lane >> 4) * 16);
    uint32_t bOff = (uint32_t)(((lane & 7) + ((lane >> 4) << 3)) * SROW + ((lane >> 3) & 1) * 16);

    float acc1[4][4][4], acc3[4][4][4];
#pragma unroll
    for (int i = 0; i < 4; i++)
#pragma unroll
        for (int j = 0; j < 4; j++)
#pragma unroll
            for (int q = 0; q < 4; q++) { acc1[i][j][q] = 0.f; acc3[i][j][q] = 0.f; }

    UP_LOAD(0, 0);
    UP_LOAD(1, 32);
    const int NCH = HDIM / 32;
#pragma unroll 1
    for (int c = 0; c < NCH; c++) {
        int buf = c % 3;
        if (c + 2 < NCH) UP_LOAD((c + 2) % 3, (c + 2) * 32);
        else CP_COMMIT();
        CP_WAIT2();
        __syncthreads();

        uint32_t s0 = sb + buf * UP_STAGE;
        uint32_t aA = s0 + UP_A  + (warpM * 64) * SROW + aOff;
        uint32_t b1 = s0 + UP_B1 + (warpN * 32) * SROW + bOff;
        uint32_t b3 = s0 + UP_B3 + (warpN * 32) * SROW + bOff;

#pragma unroll
        for (int ks = 0; ks < 2; ks++) {
            uint32_t ah[4][4];
#pragma unroll
            for (int i = 0; i < 4; i++)
                LDM4(ah[i], aA + i * 16 * SROW + ks * 32);
#pragma unroll
            for (int jp = 0; jp < 2; jp++) {
                uint32_t bb[4];
                LDM4(bb, b1 + jp * 16 * SROW + ks * 32);
#pragma unroll
                for (int i = 0; i < 4; i++) {
                    MMAH(acc1[i][2 * jp],     ah[i], bb[0], bb[1]);
                    MMAH(acc1[i][2 * jp + 1], ah[i], bb[2], bb[3]);
                }
            }
#pragma unroll
            for (int jp = 0; jp < 2; jp++) {
                uint32_t bb[4];
                LDM4(bb, b3 + jp * 16 * SROW + ks * 32);
#pragma unroll
                for (int i = 0; i < 4; i++) {
                    MMAH(acc3[i][2 * jp],     ah[i], bb[0], bb[1]);
                    MMAH(acc3[i][2 * jp + 1], ah[i], bb[2], bb[3]);
                }
            }
        }
        __syncthreads();
    }

    // epilogue: SwiGLU * weight -> G (fp16)
#pragma unroll
    for (int i = 0; i < 4; i++) {
#pragma unroll
        for (int h = 0; h < 2; h++) {
            int rloc = warpM * 64 + i * 16 + (lane >> 2) + h * 8;
            int slot = m0 + rloc;
            if (slot < mEnd) {
                float w = g_permw[slot];
                size_t rowoff = (size_t)slot * FFN;
#pragma unroll
                for (int j = 0; j < 4; j++) {
                    float d1a = acc1[i][j][2 * h], d1b = acc1[i][j][2 * h + 1];
                    float d3a = acc3[i][j][2 * h], d3b = acc3[i][j][2 * h + 1];
                    float ga = d1a / (1.f + expf(-d1a)) * d3a * w;
                    float gb = d1b / (1.f + expf(-d1b)) * d3b * w;
                    int cc = n0 + warpN * 32 + j * 8 + (lane & 3) * 2;
                    *(__half2*)(g_G + rowoff + cc) =
                        __halves2half2(__float2half(ga), __float2half(gb));
                }
            }
        }
    }
#undef UP_LOAD
}

// -------------------- down GEMM: 256M x 128N, K=FFN, pure fp16 --------------
#define DN_A   0
#define DN_B   (256 * SROW)
#define DN_STAGE (DN_B + 128 * SROW)         // 30720 B
#define DN_SMEM  (3 * DN_STAGE)

__global__ __launch_bounds__(256, 1) void down_mm() {
    int e    = blockIdx.z;
    int mEnd = g_off[e + 1];
    int m0   = g_off[e] + blockIdx.y * 256;
    if (m0 >= mEnd) return;
    int n0 = blockIdx.x * 128;

    extern __shared__ char smem[];
    uint32_t sb = smem_u32(smem);
    int tid = threadIdx.x, lane = tid & 31, wid = tid >> 5;

    int r = tid >> 2, seg = tid & 3;
    bool va[4]; int srow[4];
#pragma unroll
    for (int q = 0; q < 4; q++) {
        int slot = m0 + r + 64 * q;
        va[q]   = slot < mEnd;
        srow[q] = va[q] ? slot : 0;
    }
    size_t brow0 = ((size_t)e * HDIM + n0 + r) * FFN + seg * 8;
    size_t brow1 = ((size_t)e * HDIM + n0 + r + 64) * FFN + seg * 8;
    const __half* bp0 = g_w2 + brow0;
    const __half* bp1 = g_w2 + brow1;

#define DN_LOAD(st, kb) do {                                                    \
        uint32_t o_ = sb + (st) * DN_STAGE;                                     \
        _Pragma("unroll")                                                       \
        for (int q = 0; q < 4; q++) {                                           \
            uint32_t d_ = o_ + DN_A + (r + 64 * q) * SROW + seg * 16;           \
            const __half* sa = g_G + (size_t)srow[q] * FFN + seg * 8 + (kb);    \
            cpa16(d_, sa, va[q]);                                               \
        }                                                                       \
        uint32_t db0 = o_ + r * SROW + seg * 16;                                \
        uint32_t db1 = o_ + (r + 64) * SROW + seg * 16;                         \
        cpa16(db0 + DN_B, bp0 + (kb), true);                                    \
        cpa16(db1 + DN_B, bp1 + (kb), true);                                    \
        CP_COMMIT();                                                            \
    } while (0)

    int warpM = wid & 3, warpN = wid >> 2;
    uint32_t aOff = (uint32_t)((lane & 15) * SROW + (lane >> 4) * 16);
    uint32_t bOff = (uint32_t)(((lane & 7) + ((lane >> 4) << 3)) * SROW + ((lane >> 3) & 1) * 16);

    float acc[4][8][4];
#pragma unroll
    for (int i = 0; i < 4; i++)
#pragma unroll
        for (int j = 0; j < 8; j++)
#pragma unroll
            for (int q = 0; q < 4; q++) acc[i][j][q] = 0.f;

    DN_LOAD(0, 0);
    DN_LOAD(1, 32);
    const int NCH = FFN / 32;
#pragma unroll 1
    for (int c = 0; c < NCH; c++) {
        int buf = c % 3;
        if (c + 2 < NCH) DN_LOAD((c + 2) % 3, (c + 2) * 32);
        else CP_COMMIT();
        CP_WAIT2();
        __syncthreads();

        uint32_t s0 = sb + buf * DN_STAGE;
        uint32_t aA = s0 + DN_A + (warpM * 64) * SROW + aOff;
        uint32_t bB = s0 + DN_B + (warpN * 64) * SROW + bOff;

#pragma unroll
        for (int ks = 0; ks < 2; ks++) {
            uint32_t ah[4][4];
#pragma unroll
            for (int i = 0; i < 4; i++)
                LDM4(ah[i], aA + i * 16 * SROW + ks * 32);
#pragma unroll
            for (int jp = 0; jp < 4; jp++) {
                uint32_t bb[4];
                LDM4(bb, bB + jp * 16 * SROW + ks * 32);
#pragma unroll
                for (int i = 0; i < 4; i++) {
                    MMAH(acc[i][2 * jp],     ah[i], bb[0], bb[1]);
                    MMAH(acc[i][2 * jp + 1], ah[i], bb[2], bb[3]);
                }
            }
        }
        __syncthreads();
    }

#pragma unroll
    for (int i = 0; i < 4; i++) {
#pragma unroll
        for (int h = 0; h < 2; h++) {
            int rloc = warpM * 64 + i * 16 + (lane >> 2) + h * 8;
            int slot = m0 + rloc;
            if (slot < mEnd) {
                float* yrow = g_Y + (size_t)slot * HDIM;
#pragma unroll
                for (int j = 0; j < 8; j++) {
                    int cc = n0 + warpN * 64 + j * 8 + (lane & 3) * 2;
                    *(float2*)(yrow + cc) =
                        make_float2(acc[i][j][2 * h], acc[i][j][2 * h + 1]);
                }
            }
        }
    }
#undef DN_LOAD
}

// -------------------- combine --------------------
__global__ void combine_kernel(float* __restrict__ out) {
    int idx = blockIdx.x * blockDim.x + threadIdx.x;
    if (idx >= T * (HDIM / 4)) return;
    int t  = idx / (HDIM / 4);
    int hq = idx % (HDIM / 4);
    int s0 = g_slot[t * 2 + 0];
    int s1 = g_slot[t * 2 + 1];
    float4 a = *(const float4*)&g_Y[(size_t)s0 * HDIM + hq * 4];
    float4 b = *(const float4*)&g_Y[(size_t)s1 * HDIM + hq * 4];
    *(float4*)&out[(size_t)t * HDIM + hq * 4] =
        make_float4(a.x + b.x, a.y + b.y, a.z + b.z, a.w + b.w);
}

// -------------------- launcher --------------------
extern "C" void kernel_launch(void* const* d_in, const int* in_sizes, int n_in,
                              void* d_out, int out_size) {
    const float* x    = (const float*)d_in[0];
    const float* Wg   = (const float*)d_in[1];
    const float* W1   = (const float*)d_in[2];
    const float* W2   = (const float*)d_in[3];
    const float* W3   = (const float*)d_in[4];
    const float* bias = (const float*)d_in[5];
    float* out = (float*)d_out;

    cudaFuncSetAttribute(up_mm,   cudaFuncAttributeMaxDynamicSharedMemorySize, UP_SMEM);
    cudaFuncSetAttribute(down_mm, cudaFuncAttributeMaxDynamicSharedMemorySize, DN_SMEM);

    init_kernel<<<1, 32>>>();                                   // 0
    {
        size_t nx = (size_t)T * HDIM / 4, nw = (size_t)NEXP * FFN * HDIM / 4;
        size_t total = nx + 3 * nw;
        convert_all<<<(unsigned)((total + 255) / 256), 256>>>(x, W1, W3, W2);  // 1
    }
    router_kernel<<<T / 8, 256>>>(x, Wg, bias);                 // 2
    offsets_kernel<<<1, 32>>>();                                // 3
    scatter_kernel<<<(T + 255) / 256, 256>>>();                 // 4

    dim3 upGrid(FFN / 64, T / 256, NEXP);
    up_mm<<<upGrid, 256, UP_SMEM>>>();                          // 5

    dim3 dnGrid(HDIM / 128, T / 256, NEXP);
    down_mm<<<dnGrid, 256, DN_SMEM>>>();                        // 6

    combine_kernel<<<(T * (HDIM / 4) + 255) / 256, 256>>>(out); // 7
}